// round 1
// baseline (speedup 1.0000x reference)
#include <cuda_runtime.h>
#include <stdint.h>

#define NN 100000
#define EE 1600000
// dims: IN=64, HID=128, OUT=64

// ---------------- device scratch (no allocation allowed) ----------------
__device__ int g_idx64;
__device__ __align__(16) int   g_src[EE];
__device__ __align__(16) int   g_dst[EE];
__device__ __align__(16) int   g_deg[NN];
__device__ __align__(16) float g_dinv[NN];
__device__ __align__(16) float g_agg1[(size_t)NN * 64];
__device__ __align__(16) float g_x1  [(size_t)NN * 128];
__device__ __align__(16) float g_agg2[(size_t)NN * 128];
__device__ __align__(16) float g_x2  [(size_t)NN * 128];
__device__ __align__(16) float g_x3  [(size_t)NN * 128];

// ---------------- index dtype detection ----------------
// If src is really int32, reading it as int64 pairs two random values in
// [0,100000): the high word is nonzero with prob ~1-1e-5 per entry, so 32
// entries misclassify with prob ~1e-160.
__global__ void k_detect(const void* srcp) {
    const long long* s = (const long long*)srcp;
    int ok = 1;
    for (int i = 0; i < 32; i++) {
        long long v = s[i];
        if (v < 0 || v >= NN) ok = 0;
    }
    g_idx64 = ok;
}

// ---------------- zero the accumulators + degree ----------------
__global__ void k_zero() {
    const int stride = gridDim.x * blockDim.x;
    const int t0 = blockIdx.x * blockDim.x + threadIdx.x;
    float4 z = make_float4(0.f, 0.f, 0.f, 0.f);
    float4* a1 = (float4*)g_agg1;
    float4* a2 = (float4*)g_agg2;
    const int n1 = NN * 64 / 4;
    const int n2 = NN * 128 / 4;
    for (int i = t0; i < n1; i += stride) a1[i] = z;
    for (int i = t0; i < n2; i += stride) a2[i] = z;
    for (int i = t0; i < NN; i += stride) g_deg[i] = 0;
}

// ---------------- convert indices to int32 + degree count ----------------
__global__ void k_cvt(const void* srcp, const void* dstp) {
    int e = blockIdx.x * blockDim.x + threadIdx.x;
    if (e >= EE) return;
    int s, d;
    if (g_idx64) {
        s = (int)((const long long*)srcp)[e];
        d = (int)((const long long*)dstp)[e];
    } else {
        s = ((const int*)srcp)[e];
        d = ((const int*)dstp)[e];
    }
    g_src[e] = s;
    g_dst[e] = d;
    atomicAdd(&g_deg[d], 1);
}

__global__ void k_dinv() {
    int n = blockIdx.x * blockDim.x + threadIdx.x;
    if (n < NN) g_dinv[n] = 1.0f / fmaxf((float)g_deg[n], 1.0f);
}

// ---------------- edge scatter: agg[dst] += x[src] (vec4 reductions) ----
// LOGV: log2(float4 vectors per row). 4 -> 64-wide rows, 5 -> 128-wide rows.
template <int LOGV>
__global__ void k_scatter(const float4* __restrict__ x, float* __restrict__ agg) {
    const int VPR = 1 << LOGV;
    int idx = blockIdx.x * blockDim.x + threadIdx.x;
    if (idx >= (EE << LOGV)) return;
    int e = idx >> LOGV;
    int j = idx & (VPR - 1);
    int s = g_src[e];
    int d = g_dst[e];
    float4 v = x[(size_t)s * VPR + j];
    float* p = agg + ((size_t)d * VPR + j) * 4;
    asm volatile("red.global.add.v4.f32 [%0], {%1,%2,%3,%4};"
                 :: "l"(p), "f"(v.x), "f"(v.y), "f"(v.z), "f"(v.w)
                 : "memory");
}

// ---------------- fused dense layer ----------------
// out[r][:] = act( [A0[r] | dinv[r]*A1[r]] @ [B0;B1] + bias )
// A0 row stride = K0, A1 row stride = K-K0. Tile: 128 rows x NCOL cols,
// 256 threads, 8 x (NCOL/16) microtile per thread, K chunked by 32.
template <int K, int K0, int NCOL, bool RELU>
__global__ __launch_bounds__(256) void k_gemm(
    const float* __restrict__ A0, const float* __restrict__ A1,
    const float* __restrict__ B0, const float* __restrict__ B1,
    const float* __restrict__ bias, float* __restrict__ out) {
    constexpr int CPT = NCOL / 16;  // cols per thread (8 or 4)
    __shared__ float As[128][33];   // padded: conflict-free writes & broadcast reads
    __shared__ float Bs[32][NCOL];

    const int tid = threadIdx.x;
    const int tc = tid & 15;
    const int tr = tid >> 4;
    const int rowBase = blockIdx.x * 128;

    float acc[8][CPT];
#pragma unroll
    for (int i = 0; i < 8; i++)
#pragma unroll
        for (int j = 0; j < CPT; j++) acc[i][j] = 0.f;

    for (int kc = 0; kc < K; kc += 32) {
        // stage A tile (coalesced by k)
#pragma unroll
        for (int x = tid; x < 128 * 32; x += 256) {
            int r = x >> 5, k = x & 31;
            int gr = rowBase + r, gk = kc + k;
            float v = 0.f;
            if (gr < NN) {
                if (gk < K0)
                    v = A0[(size_t)gr * K0 + gk];
                else
                    v = A1[(size_t)gr * (K - K0) + (gk - K0)] * g_dinv[gr];
            }
            As[r][k] = v;
        }
        // stage B tile
#pragma unroll
        for (int x = tid; x < 32 * NCOL; x += 256) {
            int k = x / NCOL, j = x % NCOL;
            int gk = kc + k;
            Bs[k][j] = (gk < K0) ? B0[gk * NCOL + j] : B1[(gk - K0) * NCOL + j];
        }
        __syncthreads();

#pragma unroll
        for (int k = 0; k < 32; k++) {
            float a[8], b[CPT];
#pragma unroll
            for (int i = 0; i < 8; i++) a[i] = As[tr * 8 + i][k];
#pragma unroll
            for (int j = 0; j < CPT; j++) b[j] = Bs[k][tc * CPT + j];
#pragma unroll
            for (int i = 0; i < 8; i++)
#pragma unroll
                for (int j = 0; j < CPT; j++) acc[i][j] = fmaf(a[i], b[j], acc[i][j]);
        }
        __syncthreads();
    }

    float bb[CPT];
#pragma unroll
    for (int j = 0; j < CPT; j++) bb[j] = bias[tc * CPT + j];

#pragma unroll
    for (int i = 0; i < 8; i++) {
        int gr = rowBase + tr * 8 + i;
        if (gr < NN) {
            float v[CPT];
#pragma unroll
            for (int j = 0; j < CPT; j++) {
                float t = acc[i][j] + bb[j];
                v[j] = RELU ? fmaxf(t, 0.f) : t;
            }
            float* op = out + (size_t)gr * NCOL + tc * CPT;
#pragma unroll
            for (int j = 0; j < CPT; j += 4)
                *(float4*)(op + j) = make_float4(v[j], v[j + 1], v[j + 2], v[j + 3]);
        }
    }
}

// ---------------- launch ----------------
extern "C" void kernel_launch(void* const* d_in, const int* in_sizes, int n_in,
                              void* d_out, int out_size) {
    const float* features = (const float*)d_in[0];
    const float* Wn1 = (const float*)d_in[1];
    const float* Ws1 = (const float*)d_in[2];
    const float* b1  = (const float*)d_in[3];
    const float* Wn2 = (const float*)d_in[4];
    const float* Ws2 = (const float*)d_in[5];
    const float* b2  = (const float*)d_in[6];
    const float* Wm1 = (const float*)d_in[7];
    const float* bm1 = (const float*)d_in[8];
    const float* Wm2 = (const float*)d_in[9];
    const float* bm2 = (const float*)d_in[10];
    const void*  src = d_in[11];
    const void*  dst = d_in[12];
    float* out = (float*)d_out;

    float *p_agg1, *p_agg2, *p_x1, *p_x2, *p_x3;
    cudaGetSymbolAddress((void**)&p_agg1, g_agg1);
    cudaGetSymbolAddress((void**)&p_agg2, g_agg2);
    cudaGetSymbolAddress((void**)&p_x1, g_x1);
    cudaGetSymbolAddress((void**)&p_x2, g_x2);
    cudaGetSymbolAddress((void**)&p_x3, g_x3);

    const int GEMM_BLOCKS = (NN + 127) / 128;  // 782

    k_detect<<<1, 1>>>(src);
    k_zero<<<2048, 256>>>();
    k_cvt<<<(EE + 255) / 256, 256>>>(src, dst);
    k_dinv<<<(NN + 255) / 256, 256>>>();

    // layer 1: aggregate features (64-wide), then fused dense
    k_scatter<4><<<(EE * 16) / 256, 256>>>((const float4*)features, p_agg1);
    k_gemm<128, 64, 128, true><<<GEMM_BLOCKS, 256>>>(features, p_agg1, Ws1, Wn1, b1, p_x1);

    // layer 2: aggregate x1 (128-wide), then fused dense
    k_scatter<5><<<(EE * 32) / 256, 256>>>((const float4*)p_x1, p_agg2);
    k_gemm<256, 128, 128, true><<<GEMM_BLOCKS, 256>>>(p_x1, p_agg2, Ws2, Wn2, b2, p_x2);

    // MLP head
    k_gemm<128, 128, 128, true ><<<GEMM_BLOCKS, 256>>>(p_x2, p_x2, Wm1, Wm1, bm1, p_x3);
    k_gemm<128, 128, 64,  false><<<GEMM_BLOCKS, 256>>>(p_x3, p_x3, Wm2, Wm2, bm2, out);
}

// round 3
// speedup vs baseline: 1.0861x; 1.0861x over previous
#include <cuda_runtime.h>
#include <stdint.h>

#define NN 100000
#define EE 1600000
// dims: IN=64, HID=128, OUT=64

// ---------------- device scratch (no allocation allowed) ----------------
__device__ int g_idx64;
__device__ __align__(16) int   g_src[EE];
__device__ __align__(16) int   g_dst[EE];
__device__ __align__(16) int   g_deg[NN];
__device__ __align__(16) float g_dinv[NN];
__device__ __align__(16) float g_agg1[(size_t)NN * 64];
__device__ __align__(16) float g_x1  [(size_t)NN * 128];
__device__ __align__(16) float g_agg2[(size_t)NN * 128];
__device__ __align__(16) float g_x2  [(size_t)NN * 128];
__device__ __align__(16) float g_x3  [(size_t)NN * 128];

// ---------------- index dtype detection ----------------
// If src is really int32, reading it as int64 pairs two random values in
// [0,100000): misclassification prob over 32 entries ~1e-160.
__global__ void k_detect(const void* srcp) {
    const long long* s = (const long long*)srcp;
    int ok = 1;
    for (int i = 0; i < 32; i++) {
        long long v = s[i];
        if (v < 0 || v >= NN) ok = 0;
    }
    g_idx64 = ok;
}

// ---------------- zero the accumulators + degree ----------------
__global__ void k_zero() {
    const int stride = gridDim.x * blockDim.x;
    const int t0 = blockIdx.x * blockDim.x + threadIdx.x;
    float4 z = make_float4(0.f, 0.f, 0.f, 0.f);
    float4* a1 = (float4*)g_agg1;
    float4* a2 = (float4*)g_agg2;
    const int n1 = NN * 64 / 4;
    const int n2 = NN * 128 / 4;
    for (int i = t0; i < n1; i += stride) a1[i] = z;
    for (int i = t0; i < n2; i += stride) a2[i] = z;
    for (int i = t0; i < NN; i += stride) g_deg[i] = 0;
}

// ---------------- convert indices to int32 + degree count ----------------
__global__ void k_cvt(const void* srcp, const void* dstp) {
    int e = blockIdx.x * blockDim.x + threadIdx.x;
    if (e >= EE) return;
    int s, d;
    if (g_idx64) {
        s = (int)((const long long*)srcp)[e];
        d = (int)((const long long*)dstp)[e];
    } else {
        s = ((const int*)srcp)[e];
        d = ((const int*)dstp)[e];
    }
    g_src[e] = s;
    g_dst[e] = d;
    atomicAdd(&g_deg[d], 1);
}

__global__ void k_dinv() {
    int n = blockIdx.x * blockDim.x + threadIdx.x;
    if (n < NN) g_dinv[n] = 1.0f / fmaxf((float)g_deg[n], 1.0f);
}

// ---------------- edge scatter: agg[dst] += x[src] (vec4 reductions) ----
template <int LOGV>
__global__ void k_scatter(const float4* __restrict__ x, float* __restrict__ agg) {
    const int VPR = 1 << LOGV;
    int idx = blockIdx.x * blockDim.x + threadIdx.x;
    if (idx >= (EE << LOGV)) return;
    int e = idx >> LOGV;
    int j = idx & (VPR - 1);
    int s = g_src[e];
    int d = g_dst[e];
    float4 v = x[(size_t)s * VPR + j];
    float* p = agg + ((size_t)d * VPR + j) * 4;
    asm volatile("red.global.add.v4.f32 [%0], {%1,%2,%3,%4};"
                 :: "l"(p), "f"(v.x), "f"(v.y), "f"(v.z), "f"(v.w)
                 : "memory");
}

// ---------------- 3xTF32 tensor-core fused dense layer ----------------
// out[r][:] = act( [A0[r] | dinv[r]*A1[r]] @ [B0;B1] + bias )
// Each fp32 value is split a = hi + lo (hi = tf32(a), lo = tf32(a - hi));
// product accumulated as hi*hi + hi*lo + lo*hi -> ~fp32 accuracy on the
// tensor pipe. Tile: 128 rows x NCOL cols per block, 256 threads (8 warps).

__device__ __forceinline__ void mma_tf32(float c[4], uint32_t a0, uint32_t a1,
                                         uint32_t a2, uint32_t a3,
                                         uint32_t b0, uint32_t b1) {
    asm volatile(
        "mma.sync.aligned.m16n8k8.row.col.f32.tf32.tf32.f32 "
        "{%0,%1,%2,%3}, {%4,%5,%6,%7}, {%8,%9}, {%0,%1,%2,%3};"
        : "+f"(c[0]), "+f"(c[1]), "+f"(c[2]), "+f"(c[3])
        : "r"(a0), "r"(a1), "r"(a2), "r"(a3), "r"(b0), "r"(b1));
}

__device__ __forceinline__ uint32_t f2tf32(float x) {
    uint32_t r;
    asm("cvt.rna.tf32.f32 %0, %1;" : "=r"(r) : "f"(x));
    return r;
}

__device__ __forceinline__ void split_tf32(float x, uint32_t& hi, uint32_t& lo) {
    hi = f2tf32(x);
    lo = f2tf32(x - __uint_as_float(hi));
}

template <int K, int K0, int NCOL, bool RELU>
__global__ __launch_bounds__(256) void k_gemm_tc(
    const float* __restrict__ A0, const float* __restrict__ A1,
    const float* __restrict__ B0, const float* __restrict__ B1,
    const float* __restrict__ bias, float* __restrict__ out) {
    constexpr int MT = (NCOL == 128) ? 2 : 1;  // 16-row mma tiles per warp
    constexpr int NT = 8;                       // 8-col mma tiles per warp (64 cols)
    constexpr int AS_STRIDE = 36;   // (4g+t)%32 distinct -> conflict-free A frags
    constexpr int BS_STRIDE = 136;  // (8t+g)%32 distinct -> conflict-free B frags

    __shared__ float As[128 * AS_STRIDE];
    __shared__ float Bs[32 * BS_STRIDE];

    const int tid = threadIdx.x;
    const int w = tid >> 5;
    const int lane = tid & 31;
    const int g = lane >> 2;       // groupID (0..7)
    const int t = lane & 3;        // threadID_in_group (0..3)
    const int rowBase = blockIdx.x * 128;

    const int rbase = (NCOL == 128) ? (w & 3) * 32 : w * 16;  // warp row offset
    const int cbase = (NCOL == 128) ? (w >> 2) * 64 : 0;      // warp col offset

    float acc[MT][NT][4];
#pragma unroll
    for (int mt = 0; mt < MT; mt++)
#pragma unroll
        for (int nt = 0; nt < NT; nt++)
#pragma unroll
            for (int i = 0; i < 4; i++) acc[mt][nt][i] = 0.f;

    for (int kc = 0; kc < K; kc += 32) {
        // stage A tile: 128 x 32 (self-features | dinv-scaled aggregates)
#pragma unroll
        for (int x = tid; x < 128 * 32; x += 256) {
            int r = x >> 5, k = x & 31;
            int gr = rowBase + r, gk = kc + k;
            float v = 0.f;
            if (gr < NN) {
                if (gk < K0)
                    v = A0[(size_t)gr * K0 + gk];
                else
                    v = A1[(size_t)gr * (K - K0) + (gk - K0)] * g_dinv[gr];
            }
            As[r * AS_STRIDE + k] = v;
        }
        // stage B tile: 32 x NCOL
#pragma unroll
        for (int x = tid; x < 32 * NCOL; x += 256) {
            int k = x / NCOL, j = x % NCOL;
            int gk = kc + k;
            Bs[k * BS_STRIDE + j] =
                (gk < K0) ? B0[gk * NCOL + j] : B1[(gk - K0) * NCOL + j];
        }
        __syncthreads();

#pragma unroll
        for (int k8 = 0; k8 < 4; k8++) {
            const int kk = k8 * 8;
            // B fragments, split hi/lo (shared across M tiles)
            uint32_t bfh[NT][2], bfl[NT][2];
#pragma unroll
            for (int nt = 0; nt < NT; nt++) {
                int col = cbase + nt * 8 + g;
                split_tf32(Bs[(kk + t) * BS_STRIDE + col], bfh[nt][0], bfl[nt][0]);
                split_tf32(Bs[(kk + t + 4) * BS_STRIDE + col], bfh[nt][1], bfl[nt][1]);
            }
#pragma unroll
            for (int mt = 0; mt < MT; mt++) {
                const float* ap = As + (rbase + mt * 16) * AS_STRIDE + kk;
                uint32_t ah[4], al[4];
                split_tf32(ap[g * AS_STRIDE + t],           ah[0], al[0]);
                split_tf32(ap[(g + 8) * AS_STRIDE + t],     ah[1], al[1]);
                split_tf32(ap[g * AS_STRIDE + t + 4],       ah[2], al[2]);
                split_tf32(ap[(g + 8) * AS_STRIDE + t + 4], ah[3], al[3]);
#pragma unroll
                for (int nt = 0; nt < NT; nt++) {
                    mma_tf32(acc[mt][nt], ah[0], ah[1], ah[2], ah[3],
                             bfh[nt][0], bfh[nt][1]);
                    mma_tf32(acc[mt][nt], ah[0], ah[1], ah[2], ah[3],
                             bfl[nt][0], bfl[nt][1]);
                    mma_tf32(acc[mt][nt], al[0], al[1], al[2], al[3],
                             bfh[nt][0], bfh[nt][1]);
                }
            }
        }
        __syncthreads();
    }

    // epilogue: bias + optional relu, write float2 pairs
#pragma unroll
    for (int mt = 0; mt < MT; mt++) {
#pragma unroll
        for (int nt = 0; nt < NT; nt++) {
            int col = cbase + nt * 8 + t * 2;
            float b0 = bias[col], b1 = bias[col + 1];
#pragma unroll
            for (int half = 0; half < 2; half++) {
                int gr = rowBase + rbase + mt * 16 + g + half * 8;
                if (gr < NN) {
                    float v0 = acc[mt][nt][half * 2 + 0] + b0;
                    float v1 = acc[mt][nt][half * 2 + 1] + b1;
                    if (RELU) { v0 = fmaxf(v0, 0.f); v1 = fmaxf(v1, 0.f); }
                    *(float2*)(out + (size_t)gr * NCOL + col) = make_float2(v0, v1);
                }
            }
        }
    }
}

// ---------------- launch ----------------
extern "C" void kernel_launch(void* const* d_in, const int* in_sizes, int n_in,
                              void* d_out, int out_size) {
    const float* features = (const float*)d_in[0];
    const float* Wn1 = (const float*)d_in[1];
    const float* Ws1 = (const float*)d_in[2];
    const float* b1  = (const float*)d_in[3];
    const float* Wn2 = (const float*)d_in[4];
    const float* Ws2 = (const float*)d_in[5];
    const float* b2  = (const float*)d_in[6];
    const float* Wm1 = (const float*)d_in[7];
    const float* bm1 = (const float*)d_in[8];
    const float* Wm2 = (const float*)d_in[9];
    const float* bm2 = (const float*)d_in[10];
    const void*  src = d_in[11];
    const void*  dst = d_in[12];
    float* out = (float*)d_out;

    float *p_agg1, *p_agg2, *p_x1, *p_x2, *p_x3;
    cudaGetSymbolAddress((void**)&p_agg1, g_agg1);
    cudaGetSymbolAddress((void**)&p_agg2, g_agg2);
    cudaGetSymbolAddress((void**)&p_x1, g_x1);
    cudaGetSymbolAddress((void**)&p_x2, g_x2);
    cudaGetSymbolAddress((void**)&p_x3, g_x3);

    const int GEMM_BLOCKS = (NN + 127) / 128;  // 782

    k_detect<<<1, 1>>>(src);
    k_zero<<<2048, 256>>>();
    k_cvt<<<(EE + 255) / 256, 256>>>(src, dst);
    k_dinv<<<(NN + 255) / 256, 256>>>();

    // layer 1: aggregate features (64-wide), then fused dense
    k_scatter<4><<<(EE * 16) / 256, 256>>>((const float4*)features, p_agg1);
    k_gemm_tc<128, 64, 128, true><<<GEMM_BLOCKS, 256>>>(features, p_agg1, Ws1, Wn1, b1, p_x1);

    // layer 2: aggregate x1 (128-wide), then fused dense
    k_scatter<5><<<(EE * 32) / 256, 256>>>((const float4*)p_x1, p_agg2);
    k_gemm_tc<256, 128, 128, true><<<GEMM_BLOCKS, 256>>>(p_x1, p_agg2, Ws2, Wn2, b2, p_x2);

    // MLP head
    k_gemm_tc<128, 128, 128, true ><<<GEMM_BLOCKS, 256>>>(p_x2, p_x2, Wm1, Wm1, bm1, p_x3);
    k_gemm_tc<128, 128, 64,  false><<<GEMM_BLOCKS, 256>>>(p_x3, p_x3, Wm2, Wm2, bm2, out);
}

// round 4
// speedup vs baseline: 1.1219x; 1.0329x over previous
#include <cuda_runtime.h>
#include <stdint.h>

#define NN 100000
#define EE 1600000
// dims: IN=64, HID=128, OUT=64

// ---------------- device scratch (no allocation allowed) ----------------
__device__ int g_idx64;
__device__ __align__(16) int   g_deg[NN];
__device__ __align__(16) int   g_rowstart[NN + 1];
__device__ __align__(16) int   g_cur[NN];
__device__ __align__(16) int   g_adj[EE];
__device__ __align__(16) float g_h1  [(size_t)NN * 64];   // mean-aggregated features
__device__ __align__(16) float g_x1  [(size_t)NN * 128];
__device__ __align__(16) float g_h2  [(size_t)NN * 128];  // mean-aggregated x1
__device__ __align__(16) float g_x2  [(size_t)NN * 128];
__device__ __align__(16) float g_x3  [(size_t)NN * 128];

// ---------------- index dtype detection ----------------
// If src is really int32, reading it as int64 pairs two random values in
// [0,100000): misclassification prob over 32 entries ~1e-160.
__global__ void k_detect(const void* srcp) {
    const long long* s = (const long long*)srcp;
    int ok = 1;
    for (int i = 0; i < 32; i++) {
        long long v = s[i];
        if (v < 0 || v >= NN) ok = 0;
    }
    g_idx64 = ok;
}

__global__ void k_zero_deg() {
    int n = blockIdx.x * blockDim.x + threadIdx.x;
    if (n < NN) g_deg[n] = 0;
}

__device__ __forceinline__ int load_idx(const void* p, int e) {
    return g_idx64 ? (int)((const long long*)p)[e] : ((const int*)p)[e];
}

// ---------------- CSR build: count, scan, fill ----------------
__global__ void k_count(const void* dstp) {
    int e = blockIdx.x * blockDim.x + threadIdx.x;
    if (e >= EE) return;
    atomicAdd(&g_deg[load_idx(dstp, e)], 1);
}

// single block, 1024 threads: exclusive prefix sum of g_deg -> g_rowstart/g_cur
__global__ __launch_bounds__(1024) void k_scan() {
    __shared__ int warpsum[32];
    const int T = 1024;
    const int C = (NN + T - 1) / T;  // 98
    int t = threadIdx.x;
    int base = t * C;
    int s = 0;
    for (int i = 0; i < C; i++) {
        int idx = base + i;
        if (idx < NN) s += g_deg[idx];
    }
    int lane = t & 31, wid = t >> 5;
    int v = s;
#pragma unroll
    for (int o = 1; o < 32; o <<= 1) {
        int n = __shfl_up_sync(~0u, v, o);
        if (lane >= o) v += n;
    }
    if (lane == 31) warpsum[wid] = v;
    __syncthreads();
    if (wid == 0) {
        int w = warpsum[lane];
#pragma unroll
        for (int o = 1; o < 32; o <<= 1) {
            int n = __shfl_up_sync(~0u, w, o);
            if (lane >= o) w += n;
        }
        warpsum[lane] = w;
    }
    __syncthreads();
    int run = v - s + (wid > 0 ? warpsum[wid - 1] : 0);  // exclusive offset
    for (int i = 0; i < C; i++) {
        int idx = base + i;
        if (idx < NN) {
            g_rowstart[idx] = run;
            g_cur[idx] = run;
            run += g_deg[idx];
        }
    }
    if (t == T - 1) g_rowstart[NN] = EE;
}

__global__ void k_fill(const void* srcp, const void* dstp) {
    int e = blockIdx.x * blockDim.x + threadIdx.x;
    if (e >= EE) return;
    int s = load_idx(srcp, e);
    int d = load_idx(dstp, e);
    int pos = atomicAdd(&g_cur[d], 1);
    g_adj[pos] = s;
}

// ---------------- gather aggregation: h[n] = mean_{s in adj[n]} x[s] ------
// ROWV float4 per row (16 -> 64 floats, 32 -> 128 floats). One ROWV-thread
// group per node; lane l owns float4 column l; 4-way unrolled neighbor loop.
template <int ROWV>
__global__ void k_gather(const float4* __restrict__ x, float4* __restrict__ h) {
    int tid = blockIdx.x * blockDim.x + threadIdx.x;
    int node = tid / ROWV;
    int l = tid % ROWV;
    if (node >= NN) return;
    int i = g_rowstart[node];
    const int end = g_rowstart[node + 1];
    const int deg = end - i;
    float4 acc = make_float4(0.f, 0.f, 0.f, 0.f);
    for (; i + 4 <= end; i += 4) {
        int n0 = g_adj[i], n1 = g_adj[i + 1], n2 = g_adj[i + 2], n3 = g_adj[i + 3];
        float4 v0 = x[(size_t)n0 * ROWV + l];
        float4 v1 = x[(size_t)n1 * ROWV + l];
        float4 v2 = x[(size_t)n2 * ROWV + l];
        float4 v3 = x[(size_t)n3 * ROWV + l];
        acc.x += (v0.x + v1.x) + (v2.x + v3.x);
        acc.y += (v0.y + v1.y) + (v2.y + v3.y);
        acc.z += (v0.z + v1.z) + (v2.z + v3.z);
        acc.w += (v0.w + v1.w) + (v2.w + v3.w);
    }
    for (; i < end; i++) {
        float4 v = x[(size_t)g_adj[i] * ROWV + l];
        acc.x += v.x; acc.y += v.y; acc.z += v.z; acc.w += v.w;
    }
    float inv = 1.f / (float)max(deg, 1);
    acc.x *= inv; acc.y *= inv; acc.z *= inv; acc.w *= inv;
    h[(size_t)node * ROWV + l] = acc;
}

// ---------------- 3xTF32 tensor-core fused dense layer ----------------
// out[r][:] = act( [A0[r] | A1[r]] @ [B0;B1] + bias )
// fp32 split a = hi + lo on the fly; hi*hi + hi*lo + lo*hi accumulation.
// Tile: 128 rows x NCOL cols per block, 256 threads (8 warps).

__device__ __forceinline__ void mma_tf32(float c[4], uint32_t a0, uint32_t a1,
                                         uint32_t a2, uint32_t a3,
                                         uint32_t b0, uint32_t b1) {
    asm volatile(
        "mma.sync.aligned.m16n8k8.row.col.f32.tf32.tf32.f32 "
        "{%0,%1,%2,%3}, {%4,%5,%6,%7}, {%8,%9}, {%0,%1,%2,%3};"
        : "+f"(c[0]), "+f"(c[1]), "+f"(c[2]), "+f"(c[3])
        : "r"(a0), "r"(a1), "r"(a2), "r"(a3), "r"(b0), "r"(b1));
}

__device__ __forceinline__ uint32_t f2tf32(float x) {
    uint32_t r;
    asm("cvt.rna.tf32.f32 %0, %1;" : "=r"(r) : "f"(x));
    return r;
}

__device__ __forceinline__ void split_tf32(float x, uint32_t& hi, uint32_t& lo) {
    hi = f2tf32(x);
    lo = f2tf32(x - __uint_as_float(hi));
}

template <int K, int K0, int NCOL, bool RELU>
__global__ __launch_bounds__(256) void k_gemm_tc(
    const float* __restrict__ A0, const float* __restrict__ A1,
    const float* __restrict__ B0, const float* __restrict__ B1,
    const float* __restrict__ bias, float* __restrict__ out) {
    constexpr int MT = (NCOL == 128) ? 2 : 1;  // 16-row mma tiles per warp
    constexpr int NT = 8;                       // 8-col mma tiles per warp (64 cols)
    constexpr int AS_STRIDE = 36;   // (4g+t)%32 distinct -> conflict-free A frags
    constexpr int BS_STRIDE = 136;  // (8t+g)%32 distinct -> conflict-free B frags

    __shared__ float As[128 * AS_STRIDE];
    __shared__ float Bs[32 * BS_STRIDE];

    const int tid = threadIdx.x;
    const int w = tid >> 5;
    const int lane = tid & 31;
    const int g = lane >> 2;       // groupID (0..7)
    const int t = lane & 3;        // threadID_in_group (0..3)
    const int rowBase = blockIdx.x * 128;

    const int rbase = (NCOL == 128) ? (w & 3) * 32 : w * 16;  // warp row offset
    const int cbase = (NCOL == 128) ? (w >> 2) * 64 : 0;      // warp col offset

    float acc[MT][NT][4];
#pragma unroll
    for (int mt = 0; mt < MT; mt++)
#pragma unroll
        for (int nt = 0; nt < NT; nt++)
#pragma unroll
            for (int i = 0; i < 4; i++) acc[mt][nt][i] = 0.f;

    for (int kc = 0; kc < K; kc += 32) {
        // stage A tile: 128 x 32 (self-features | mean-aggregated features)
#pragma unroll
        for (int x = tid; x < 128 * 32; x += 256) {
            int r = x >> 5, k = x & 31;
            int gr = rowBase + r, gk = kc + k;
            float v = 0.f;
            if (gr < NN) {
                if (gk < K0)
                    v = A0[(size_t)gr * K0 + gk];
                else
                    v = A1[(size_t)gr * (K - K0) + (gk - K0)];
            }
            As[r * AS_STRIDE + k] = v;
        }
        // stage B tile: 32 x NCOL
#pragma unroll
        for (int x = tid; x < 32 * NCOL; x += 256) {
            int k = x / NCOL, j = x % NCOL;
            int gk = kc + k;
            Bs[k * BS_STRIDE + j] =
                (gk < K0) ? B0[gk * NCOL + j] : B1[(gk - K0) * NCOL + j];
        }
        __syncthreads();

#pragma unroll
        for (int k8 = 0; k8 < 4; k8++) {
            const int kk = k8 * 8;
            // B fragments, split hi/lo (shared across M tiles)
            uint32_t bfh[NT][2], bfl[NT][2];
#pragma unroll
            for (int nt = 0; nt < NT; nt++) {
                int col = cbase + nt * 8 + g;
                split_tf32(Bs[(kk + t) * BS_STRIDE + col], bfh[nt][0], bfl[nt][0]);
                split_tf32(Bs[(kk + t + 4) * BS_STRIDE + col], bfh[nt][1], bfl[nt][1]);
            }
#pragma unroll
            for (int mt = 0; mt < MT; mt++) {
                const float* ap = As + (rbase + mt * 16) * AS_STRIDE + kk;
                uint32_t ah[4], al[4];
                split_tf32(ap[g * AS_STRIDE + t],           ah[0], al[0]);
                split_tf32(ap[(g + 8) * AS_STRIDE + t],     ah[1], al[1]);
                split_tf32(ap[g * AS_STRIDE + t + 4],       ah[2], al[2]);
                split_tf32(ap[(g + 8) * AS_STRIDE + t + 4], ah[3], al[3]);
#pragma unroll
                for (int nt = 0; nt < NT; nt++) {
                    mma_tf32(acc[mt][nt], ah[0], ah[1], ah[2], ah[3],
                             bfh[nt][0], bfh[nt][1]);
                    mma_tf32(acc[mt][nt], ah[0], ah[1], ah[2], ah[3],
                             bfl[nt][0], bfl[nt][1]);
                    mma_tf32(acc[mt][nt], al[0], al[1], al[2], al[3],
                             bfh[nt][0], bfh[nt][1]);
                }
            }
        }
        __syncthreads();
    }

    // epilogue: bias + optional relu, write float2 pairs
#pragma unroll
    for (int mt = 0; mt < MT; mt++) {
#pragma unroll
        for (int nt = 0; nt < NT; nt++) {
            int col = cbase + nt * 8 + t * 2;
            float b0 = bias[col], b1 = bias[col + 1];
#pragma unroll
            for (int half = 0; half < 2; half++) {
                int gr = rowBase + rbase + mt * 16 + g + half * 8;
                if (gr < NN) {
                    float v0 = acc[mt][nt][half * 2 + 0] + b0;
                    float v1 = acc[mt][nt][half * 2 + 1] + b1;
                    if (RELU) { v0 = fmaxf(v0, 0.f); v1 = fmaxf(v1, 0.f); }
                    *(float2*)(out + (size_t)gr * NCOL + col) = make_float2(v0, v1);
                }
            }
        }
    }
}

// ---------------- launch ----------------
extern "C" void kernel_launch(void* const* d_in, const int* in_sizes, int n_in,
                              void* d_out, int out_size) {
    const float* features = (const float*)d_in[0];
    const float* Wn1 = (const float*)d_in[1];
    const float* Ws1 = (const float*)d_in[2];
    const float* b1  = (const float*)d_in[3];
    const float* Wn2 = (const float*)d_in[4];
    const float* Ws2 = (const float*)d_in[5];
    const float* b2  = (const float*)d_in[6];
    const float* Wm1 = (const float*)d_in[7];
    const float* bm1 = (const float*)d_in[8];
    const float* Wm2 = (const float*)d_in[9];
    const float* bm2 = (const float*)d_in[10];
    const void*  src = d_in[11];
    const void*  dst = d_in[12];
    float* out = (float*)d_out;

    float *p_h1, *p_h2, *p_x1, *p_x2, *p_x3;
    cudaGetSymbolAddress((void**)&p_h1, g_h1);
    cudaGetSymbolAddress((void**)&p_h2, g_h2);
    cudaGetSymbolAddress((void**)&p_x1, g_x1);
    cudaGetSymbolAddress((void**)&p_x2, g_x2);
    cudaGetSymbolAddress((void**)&p_x3, g_x3);

    const int GEMM_BLOCKS = (NN + 127) / 128;  // 782
    const int EB = (EE + 255) / 256;

    // CSR build
    k_detect<<<1, 1>>>(src);
    k_zero_deg<<<(NN + 255) / 256, 256>>>();
    k_count<<<EB, 256>>>(dst);
    k_scan<<<1, 1024>>>();
    k_fill<<<EB, 256>>>(src, dst);

    // layer 1: mean-aggregate features (64-wide), then fused dense
    k_gather<16><<<(NN * 16 + 255) / 256, 256>>>((const float4*)features, (float4*)p_h1);
    k_gemm_tc<128, 64, 128, true><<<GEMM_BLOCKS, 256>>>(features, p_h1, Ws1, Wn1, b1, p_x1);

    // layer 2: mean-aggregate x1 (128-wide), then fused dense
    k_gather<32><<<(NN * 32 + 255) / 256, 256>>>((const float4*)p_x1, (float4*)p_h2);
    k_gemm_tc<256, 128, 128, true><<<GEMM_BLOCKS, 256>>>(p_x1, p_h2, Ws2, Wn2, b2, p_x2);

    // MLP head
    k_gemm_tc<128, 128, 128, true ><<<GEMM_BLOCKS, 256>>>(p_x2, p_x2, Wm1, Wm1, bm1, p_x3);
    k_gemm_tc<128, 128, 64,  false><<<GEMM_BLOCKS, 256>>>(p_x3, p_x3, Wm2, Wm2, bm2, out);
}

// round 5
// speedup vs baseline: 1.6946x; 1.5105x over previous
#include <cuda_runtime.h>
#include <stdint.h>

#define NN 100000
#define EE 1600000
// dims: IN=64, HID=128, OUT=64

// ---------------- device scratch (no allocation allowed) ----------------
__device__ int g_idx64;
__device__ __align__(16) int   g_deg[NN];
__device__ __align__(16) int   g_rowstart[NN + 1];
__device__ __align__(16) int   g_cur[NN];
__device__ __align__(16) int   g_adj[EE];
__device__ __align__(16) int   g_blocksum[128];
__device__ __align__(16) int   g_blockoff[128];
__device__ __align__(16) float g_h1  [(size_t)NN * 64];   // mean-aggregated features
__device__ __align__(16) float g_x1  [(size_t)NN * 128];
__device__ __align__(16) float g_h2  [(size_t)NN * 128];  // mean-aggregated x1
__device__ __align__(16) float g_x2  [(size_t)NN * 128];
__device__ __align__(16) float g_x3  [(size_t)NN * 128];

// ---------------- index dtype detection ----------------
__global__ void k_detect(const void* srcp) {
    const long long* s = (const long long*)srcp;
    int ok = 1;
    for (int i = 0; i < 32; i++) {
        long long v = s[i];
        if (v < 0 || v >= NN) ok = 0;
    }
    g_idx64 = ok;
}

__global__ void k_zero_deg() {
    int n = blockIdx.x * blockDim.x + threadIdx.x;
    if (n < NN) g_deg[n] = 0;
}

__device__ __forceinline__ int load_idx(const void* p, int e) {
    return g_idx64 ? (int)((const long long*)p)[e] : ((const int*)p)[e];
}

// ---------------- CSR build: count, 3-phase scan, fill ----------------
__global__ void k_count(const void* dstp) {
    int e = blockIdx.x * blockDim.x + threadIdx.x;
    if (e >= EE) return;
    atomicAdd(&g_deg[load_idx(dstp, e)], 1);
}

// phase 1: per-block (1024 elems) sums
__global__ __launch_bounds__(1024) void k_scan1() {
    __shared__ int ws[32];
    int t = threadIdx.x, lane = t & 31, wid = t >> 5;
    int idx = blockIdx.x * 1024 + t;
    int v = (idx < NN) ? g_deg[idx] : 0;
    int s = v;
#pragma unroll
    for (int o = 16; o > 0; o >>= 1) s += __shfl_down_sync(~0u, s, o);
    if (lane == 0) ws[wid] = s;
    __syncthreads();
    if (wid == 0) {
        int x = (lane < 32) ? ws[lane] : 0;
#pragma unroll
        for (int o = 16; o > 0; o >>= 1) x += __shfl_down_sync(~0u, x, o);
        if (lane == 0) g_blocksum[blockIdx.x] = x;
    }
}

// phase 2: single block, exclusive scan of NB block sums
__global__ __launch_bounds__(128) void k_scan2(int nb) {
    __shared__ int ws[4];
    int t = threadIdx.x, lane = t & 31, wid = t >> 5;
    int v = (t < nb) ? g_blocksum[t] : 0;
    int inc = v;
#pragma unroll
    for (int o = 1; o < 32; o <<= 1) {
        int n = __shfl_up_sync(~0u, inc, o);
        if (lane >= o) inc += n;
    }
    if (lane == 31) ws[wid] = inc;
    __syncthreads();
    int add = 0;
    for (int i = 0; i < wid; i++) add += ws[i];
    if (t < nb) g_blockoff[t] = inc - v + add;  // exclusive
}

// phase 3: per-block exclusive scan + global offset -> rowstart/cur
__global__ __launch_bounds__(1024) void k_scan3() {
    __shared__ int ws[32];
    int t = threadIdx.x, lane = t & 31, wid = t >> 5;
    int idx = blockIdx.x * 1024 + t;
    int v = (idx < NN) ? g_deg[idx] : 0;
    int inc = v;
#pragma unroll
    for (int o = 1; o < 32; o <<= 1) {
        int n = __shfl_up_sync(~0u, inc, o);
        if (lane >= o) inc += n;
    }
    if (lane == 31) ws[wid] = inc;
    __syncthreads();
    if (wid == 0) {
        int x = ws[lane];
#pragma unroll
        for (int o = 1; o < 32; o <<= 1) {
            int n = __shfl_up_sync(~0u, x, o);
            if (lane >= o) x += n;
        }
        ws[lane] = x;
    }
    __syncthreads();
    int exc = inc - v + (wid > 0 ? ws[wid - 1] : 0) + g_blockoff[blockIdx.x];
    if (idx < NN) {
        g_rowstart[idx] = exc;
        g_cur[idx] = exc;
    }
    if (idx == NN - 1) g_rowstart[NN] = EE;
}

__global__ void k_fill(const void* srcp, const void* dstp) {
    int e = blockIdx.x * blockDim.x + threadIdx.x;
    if (e >= EE) return;
    int s = load_idx(srcp, e);
    int d = load_idx(dstp, e);
    int pos = atomicAdd(&g_cur[d], 1);
    g_adj[pos] = s;
}

// ---------------- gather aggregation: h[n] = mean_{s in adj[n]} x[s] ------
template <int ROWV>
__global__ void k_gather(const float4* __restrict__ x, float4* __restrict__ h) {
    int tid = blockIdx.x * blockDim.x + threadIdx.x;
    int node = tid / ROWV;
    int l = tid % ROWV;
    if (node >= NN) return;
    int i = g_rowstart[node];
    const int end = g_rowstart[node + 1];
    const int deg = end - i;
    float4 acc = make_float4(0.f, 0.f, 0.f, 0.f);
    for (; i + 4 <= end; i += 4) {
        int n0 = g_adj[i], n1 = g_adj[i + 1], n2 = g_adj[i + 2], n3 = g_adj[i + 3];
        float4 v0 = x[(size_t)n0 * ROWV + l];
        float4 v1 = x[(size_t)n1 * ROWV + l];
        float4 v2 = x[(size_t)n2 * ROWV + l];
        float4 v3 = x[(size_t)n3 * ROWV + l];
        acc.x += (v0.x + v1.x) + (v2.x + v3.x);
        acc.y += (v0.y + v1.y) + (v2.y + v3.y);
        acc.z += (v0.z + v1.z) + (v2.z + v3.z);
        acc.w += (v0.w + v1.w) + (v2.w + v3.w);
    }
    for (; i < end; i++) {
        float4 v = x[(size_t)g_adj[i] * ROWV + l];
        acc.x += v.x; acc.y += v.y; acc.z += v.z; acc.w += v.w;
    }
    float inv = 1.f / (float)max(deg, 1);
    acc.x *= inv; acc.y *= inv; acc.z *= inv; acc.w *= inv;
    h[(size_t)node * ROWV + l] = acc;
}

// ---------------- 3xTF32 tensor-core fused dense layer ----------------
// out[r][:] = act( [A0[r] | A1[r]] @ [B0;B1] + bias )
// fp32 split a = hi + lo on the fly; hi*hi + hi*lo + lo*hi accumulation.
// Tile: 128 rows x NCOL cols per block, 256 threads (8 warps), 2 CTAs/SM.

__device__ __forceinline__ void mma_tf32(float c[4], uint32_t a0, uint32_t a1,
                                         uint32_t a2, uint32_t a3,
                                         uint32_t b0, uint32_t b1) {
    asm volatile(
        "mma.sync.aligned.m16n8k8.row.col.f32.tf32.tf32.f32 "
        "{%0,%1,%2,%3}, {%4,%5,%6,%7}, {%8,%9}, {%0,%1,%2,%3};"
        : "+f"(c[0]), "+f"(c[1]), "+f"(c[2]), "+f"(c[3])
        : "r"(a0), "r"(a1), "r"(a2), "r"(a3), "r"(b0), "r"(b1));
}

__device__ __forceinline__ uint32_t f2tf32(float x) {
    uint32_t r;
    asm("cvt.rna.tf32.f32 %0, %1;" : "=r"(r) : "f"(x));
    return r;
}

__device__ __forceinline__ void split_tf32(float x, uint32_t& hi, uint32_t& lo) {
    hi = f2tf32(x);
    lo = f2tf32(x - __uint_as_float(hi));
}

template <int K, int K0, int NCOL, bool RELU>
__global__ __launch_bounds__(256, 2) void k_gemm_tc(
    const float* __restrict__ A0, const float* __restrict__ A1,
    const float* __restrict__ B0, const float* __restrict__ B1,
    const float* __restrict__ bias, float* __restrict__ out) {
    constexpr int MT = (NCOL == 128) ? 2 : 1;  // 16-row mma tiles per warp
    constexpr int NT = 8;                       // 8-col mma tiles per warp (64 cols)
    constexpr int NTG = 4;                      // tiles per register group
    constexpr int AS_STRIDE = 36;   // (4g+t)%32 distinct -> conflict-free A frags
    constexpr int BS_STRIDE = 136;  // (8t+g)%32 distinct -> conflict-free B frags

    __shared__ float As[128 * AS_STRIDE];
    __shared__ float Bs[32 * BS_STRIDE];

    const int tid = threadIdx.x;
    const int w = tid >> 5;
    const int lane = tid & 31;
    const int g = lane >> 2;       // groupID (0..7)
    const int t = lane & 3;        // threadID_in_group (0..3)
    const int rowBase = blockIdx.x * 128;

    const int rbase = (NCOL == 128) ? (w & 3) * 32 : w * 16;  // warp row offset
    const int cbase = (NCOL == 128) ? (w >> 2) * 64 : 0;      // warp col offset

    float acc[MT][NT][4];
#pragma unroll
    for (int mt = 0; mt < MT; mt++)
#pragma unroll
        for (int nt = 0; nt < NT; nt++)
#pragma unroll
            for (int i = 0; i < 4; i++) acc[mt][nt][i] = 0.f;

    for (int kc = 0; kc < K; kc += 32) {
        // stage A tile: 128 x 32 (self-features | mean-aggregated features)
#pragma unroll
        for (int x = tid; x < 128 * 32; x += 256) {
            int r = x >> 5, k = x & 31;
            int gr = rowBase + r, gk = kc + k;
            float v = 0.f;
            if (gr < NN) {
                if (gk < K0)
                    v = A0[(size_t)gr * K0 + gk];
                else
                    v = A1[(size_t)gr * (K - K0) + (gk - K0)];
            }
            As[r * AS_STRIDE + k] = v;
        }
        // stage B tile: 32 x NCOL
#pragma unroll
        for (int x = tid; x < 32 * NCOL; x += 256) {
            int k = x / NCOL, j = x % NCOL;
            int gk = kc + k;
            Bs[k * BS_STRIDE + j] =
                (gk < K0) ? B0[gk * NCOL + j] : B1[(gk - K0) * NCOL + j];
        }
        __syncthreads();

#pragma unroll
        for (int k8 = 0; k8 < 4; k8++) {
            const int kk = k8 * 8;
            // NT split into groups of NTG to bound live B-fragment registers
#pragma unroll
            for (int ng = 0; ng < NT / NTG; ng++) {
                uint32_t bfh[NTG][2], bfl[NTG][2];
#pragma unroll
                for (int j = 0; j < NTG; j++) {
                    int col = cbase + (ng * NTG + j) * 8 + g;
                    split_tf32(Bs[(kk + t) * BS_STRIDE + col], bfh[j][0], bfl[j][0]);
                    split_tf32(Bs[(kk + t + 4) * BS_STRIDE + col], bfh[j][1], bfl[j][1]);
                }
#pragma unroll
                for (int mt = 0; mt < MT; mt++) {
                    const float* ap = As + (rbase + mt * 16) * AS_STRIDE + kk;
                    uint32_t ah[4], al[4];
                    split_tf32(ap[g * AS_STRIDE + t],           ah[0], al[0]);
                    split_tf32(ap[(g + 8) * AS_STRIDE + t],     ah[1], al[1]);
                    split_tf32(ap[g * AS_STRIDE + t + 4],       ah[2], al[2]);
                    split_tf32(ap[(g + 8) * AS_STRIDE + t + 4], ah[3], al[3]);
#pragma unroll
                    for (int j = 0; j < NTG; j++) {
                        float* a = acc[mt][ng * NTG + j];
                        mma_tf32(a, ah[0], ah[1], ah[2], ah[3], bfh[j][0], bfh[j][1]);
                        mma_tf32(a, ah[0], ah[1], ah[2], ah[3], bfl[j][0], bfl[j][1]);
                        mma_tf32(a, al[0], al[1], al[2], al[3], bfh[j][0], bfh[j][1]);
                    }
                }
            }
        }
        __syncthreads();
    }

    // epilogue: bias + optional relu, write float2 pairs
#pragma unroll
    for (int mt = 0; mt < MT; mt++) {
#pragma unroll
        for (int nt = 0; nt < NT; nt++) {
            int col = cbase + nt * 8 + t * 2;
            float b0 = bias[col], b1 = bias[col + 1];
#pragma unroll
            for (int half = 0; half < 2; half++) {
                int gr = rowBase + rbase + mt * 16 + g + half * 8;
                if (gr < NN) {
                    float v0 = acc[mt][nt][half * 2 + 0] + b0;
                    float v1 = acc[mt][nt][half * 2 + 1] + b1;
                    if (RELU) { v0 = fmaxf(v0, 0.f); v1 = fmaxf(v1, 0.f); }
                    *(float2*)(out + (size_t)gr * NCOL + col) = make_float2(v0, v1);
                }
            }
        }
    }
}

// ---------------- launch ----------------
extern "C" void kernel_launch(void* const* d_in, const int* in_sizes, int n_in,
                              void* d_out, int out_size) {
    const float* features = (const float*)d_in[0];
    const float* Wn1 = (const float*)d_in[1];
    const float* Ws1 = (const float*)d_in[2];
    const float* b1  = (const float*)d_in[3];
    const float* Wn2 = (const float*)d_in[4];
    const float* Ws2 = (const float*)d_in[5];
    const float* b2  = (const float*)d_in[6];
    const float* Wm1 = (const float*)d_in[7];
    const float* bm1 = (const float*)d_in[8];
    const float* Wm2 = (const float*)d_in[9];
    const float* bm2 = (const float*)d_in[10];
    const void*  src = d_in[11];
    const void*  dst = d_in[12];
    float* out = (float*)d_out;

    float *p_h1, *p_h2, *p_x1, *p_x2, *p_x3;
    cudaGetSymbolAddress((void**)&p_h1, g_h1);
    cudaGetSymbolAddress((void**)&p_h2, g_h2);
    cudaGetSymbolAddress((void**)&p_x1, g_x1);
    cudaGetSymbolAddress((void**)&p_x2, g_x2);
    cudaGetSymbolAddress((void**)&p_x3, g_x3);

    const int GEMM_BLOCKS = (NN + 127) / 128;  // 782
    const int EB = (EE + 255) / 256;
    const int NB = (NN + 1023) / 1024;         // 98 scan blocks

    // CSR build
    k_detect<<<1, 1>>>(src);
    k_zero_deg<<<(NN + 255) / 256, 256>>>();
    k_count<<<EB, 256>>>(dst);
    k_scan1<<<NB, 1024>>>();
    k_scan2<<<1, 128>>>(NB);
    k_scan3<<<NB, 1024>>>();
    k_fill<<<EB, 256>>>(src, dst);

    // layer 1: mean-aggregate features (64-wide), then fused dense
    k_gather<16><<<(NN * 16 + 255) / 256, 256>>>((const float4*)features, (float4*)p_h1);
    k_gemm_tc<128, 64, 128, true><<<GEMM_BLOCKS, 256>>>(features, p_h1, Ws1, Wn1, b1, p_x1);

    // layer 2: mean-aggregate x1 (128-wide), then fused dense
    k_gather<32><<<(NN * 32 + 255) / 256, 256>>>((const float4*)p_x1, (float4*)p_h2);
    k_gemm_tc<256, 128, 128, true><<<GEMM_BLOCKS, 256>>>(p_x1, p_h2, Ws2, Wn2, b2, p_x2);

    // MLP head
    k_gemm_tc<128, 128, 128, true ><<<GEMM_BLOCKS, 256>>>(p_x2, p_x2, Wm1, Wm1, bm1, p_x3);
    k_gemm_tc<128, 128, 64,  false><<<GEMM_BLOCKS, 256>>>(p_x3, p_x3, Wm2, Wm2, bm2, out);
}

// round 6
// speedup vs baseline: 2.5734x; 1.5185x over previous
#include <cuda_runtime.h>
#include <cuda_fp16.h>
#include <stdint.h>

#define NN 100000
#define EE 1600000
// dims: IN=64, HID=128, OUT=64

// ---------------- device scratch (no allocation allowed) ----------------
__device__ int g_idx64;
__device__ __align__(16) int   g_deg[NN];
__device__ __align__(16) int   g_rowstart[NN + 1];
__device__ __align__(16) int   g_cur[NN];
__device__ __align__(16) int   g_adj[EE];
__device__ __align__(16) int   g_blocksum[128];
__device__ __align__(16) int   g_blockoff[128];
__device__ __align__(16) float g_h1  [(size_t)NN * 64];   // mean-aggregated features
__device__ __align__(16) float g_x1  [(size_t)NN * 128];
__device__ __align__(16) float g_h2  [(size_t)NN * 128];  // mean-aggregated x1
__device__ __align__(16) float g_x2  [(size_t)NN * 128];
__device__ __align__(16) float g_x3  [(size_t)NN * 128];

// ---------------- index dtype detection ----------------
__global__ void k_detect(const void* srcp) {
    const long long* s = (const long long*)srcp;
    int lane = threadIdx.x;
    long long v = s[lane];
    int ok = (v >= 0 && v < NN) ? 1 : 0;
    ok = __all_sync(~0u, ok);
    if (lane == 0) g_idx64 = ok;
}

__global__ void k_zero_deg() {
    int n = blockIdx.x * blockDim.x + threadIdx.x;
    if (n < NN) g_deg[n] = 0;
}

__device__ __forceinline__ int load_idx(const void* p, int e) {
    return g_idx64 ? (int)((const long long*)p)[e] : ((const int*)p)[e];
}

// ---------------- CSR build: count, 3-phase scan, fill ----------------
__global__ void k_count(const void* dstp) {
    int e = blockIdx.x * blockDim.x + threadIdx.x;
    if (e >= EE) return;
    atomicAdd(&g_deg[load_idx(dstp, e)], 1);
}

__global__ __launch_bounds__(1024) void k_scan1() {
    __shared__ int ws[32];
    int t = threadIdx.x, lane = t & 31, wid = t >> 5;
    int idx = blockIdx.x * 1024 + t;
    int s = (idx < NN) ? g_deg[idx] : 0;
#pragma unroll
    for (int o = 16; o > 0; o >>= 1) s += __shfl_down_sync(~0u, s, o);
    if (lane == 0) ws[wid] = s;
    __syncthreads();
    if (wid == 0) {
        int x = ws[lane];
#pragma unroll
        for (int o = 16; o > 0; o >>= 1) x += __shfl_down_sync(~0u, x, o);
        if (lane == 0) g_blocksum[blockIdx.x] = x;
    }
}

__global__ __launch_bounds__(128) void k_scan2(int nb) {
    __shared__ int ws[4];
    int t = threadIdx.x, lane = t & 31, wid = t >> 5;
    int v = (t < nb) ? g_blocksum[t] : 0;
    int inc = v;
#pragma unroll
    for (int o = 1; o < 32; o <<= 1) {
        int n = __shfl_up_sync(~0u, inc, o);
        if (lane >= o) inc += n;
    }
    if (lane == 31) ws[wid] = inc;
    __syncthreads();
    int add = 0;
    for (int i = 0; i < wid; i++) add += ws[i];
    if (t < nb) g_blockoff[t] = inc - v + add;  // exclusive
}

__global__ __launch_bounds__(1024) void k_scan3() {
    __shared__ int ws[32];
    int t = threadIdx.x, lane = t & 31, wid = t >> 5;
    int idx = blockIdx.x * 1024 + t;
    int v = (idx < NN) ? g_deg[idx] : 0;
    int inc = v;
#pragma unroll
    for (int o = 1; o < 32; o <<= 1) {
        int n = __shfl_up_sync(~0u, inc, o);
        if (lane >= o) inc += n;
    }
    if (lane == 31) ws[wid] = inc;
    __syncthreads();
    if (wid == 0) {
        int x = ws[lane];
#pragma unroll
        for (int o = 1; o < 32; o <<= 1) {
            int n = __shfl_up_sync(~0u, x, o);
            if (lane >= o) x += n;
        }
        ws[lane] = x;
    }
    __syncthreads();
    int exc = inc - v + (wid > 0 ? ws[wid - 1] : 0) + g_blockoff[blockIdx.x];
    if (idx < NN) {
        g_rowstart[idx] = exc;
        g_cur[idx] = exc;
    }
    if (idx == NN - 1) g_rowstart[NN] = EE;
}

__global__ void k_fill(const void* srcp, const void* dstp) {
    int e = blockIdx.x * blockDim.x + threadIdx.x;
    if (e >= EE) return;
    int s = load_idx(srcp, e);
    int d = load_idx(dstp, e);
    int pos = atomicAdd(&g_cur[d], 1);
    g_adj[pos] = s;
}

// ---------------- gather aggregation: h[n] = mean_{s in adj[n]} x[s] ------
template <int ROWV>
__global__ void k_gather(const float4* __restrict__ x, float4* __restrict__ h) {
    int tid = blockIdx.x * blockDim.x + threadIdx.x;
    int node = tid / ROWV;
    int l = tid % ROWV;
    if (node >= NN) return;
    int i = g_rowstart[node];
    const int end = g_rowstart[node + 1];
    const int deg = end - i;
    float4 acc = make_float4(0.f, 0.f, 0.f, 0.f);
    for (; i + 4 <= end; i += 4) {
        int n0 = g_adj[i], n1 = g_adj[i + 1], n2 = g_adj[i + 2], n3 = g_adj[i + 3];
        float4 v0 = x[(size_t)n0 * ROWV + l];
        float4 v1 = x[(size_t)n1 * ROWV + l];
        float4 v2 = x[(size_t)n2 * ROWV + l];
        float4 v3 = x[(size_t)n3 * ROWV + l];
        acc.x += (v0.x + v1.x) + (v2.x + v3.x);
        acc.y += (v0.y + v1.y) + (v2.y + v3.y);
        acc.z += (v0.z + v1.z) + (v2.z + v3.z);
        acc.w += (v0.w + v1.w) + (v2.w + v3.w);
    }
    for (; i < end; i++) {
        float4 v = x[(size_t)g_adj[i] * ROWV + l];
        acc.x += v.x; acc.y += v.y; acc.z += v.z; acc.w += v.w;
    }
    float inv = 1.f / (float)max(deg, 1);
    acc.x *= inv; acc.y *= inv; acc.z *= inv; acc.w *= inv;
    h[(size_t)node * ROWV + l] = acc;
}

// ---------------- FP16x2-split tensor-core fused dense layer ----------------
// out[r][:] = act( [A0[r] | A1[r]] @ [B0;B1] + bias )
// fp32 a = hi + lo (hi = fp16(a), lo = fp16(a - hi)); product accumulated as
// hi*hi + hi*lo + lo*hi via mma.m16n8k16.f32.f16.f16.f32 (lo*lo ~2^-22 dropped).
// Split happens ONCE at staging; smem holds pre-split half tiles.
// Tile: 128 rows x NCOL cols per block, 256 threads (8 warps), 2 CTAs/SM.

__device__ __forceinline__ void mma_fp16(float c[4], uint32_t a0, uint32_t a1,
                                         uint32_t a2, uint32_t a3,
                                         uint32_t b0, uint32_t b1) {
    asm volatile(
        "mma.sync.aligned.m16n8k16.row.col.f32.f16.f16.f32 "
        "{%0,%1,%2,%3}, {%4,%5,%6,%7}, {%8,%9}, {%0,%1,%2,%3};"
        : "+f"(c[0]), "+f"(c[1]), "+f"(c[2]), "+f"(c[3])
        : "r"(a0), "r"(a1), "r"(a2), "r"(a3), "r"(b0), "r"(b1));
}

__device__ __forceinline__ void split_h(float x, __half& hi, __half& lo) {
    hi = __float2half_rn(x);
    lo = __float2half_rn(x - __half2float(hi));
}

// 40-half row stride: fragment LDS bank = (g*20 + t) mod 32, all lanes distinct.
#define HSTR 40

template <int K, int K0, int NCOL, bool RELU>
__global__ __launch_bounds__(256, 2) void k_gemm_fp16x2(
    const float* __restrict__ A0, const float* __restrict__ A1,
    const float* __restrict__ B0, const float* __restrict__ B1,
    const float* __restrict__ bias, float* __restrict__ out) {
    constexpr int MT = (NCOL == 128) ? 2 : 1;  // 16-row mma tiles per warp
    constexpr int NT = 8;                       // 8-col mma tiles per warp
    constexpr int NTG = 4;                      // B tiles per register group

    __shared__ __half As_hi[128 * HSTR];
    __shared__ __half As_lo[128 * HSTR];
    __shared__ __half Bs_hi[NCOL * HSTR];   // transposed: [col][k]
    __shared__ __half Bs_lo[NCOL * HSTR];

    const int tid = threadIdx.x;
    const int w = tid >> 5;
    const int lane = tid & 31;
    const int g = lane >> 2;
    const int t = lane & 3;
    const int rowBase = blockIdx.x * 128;

    const int rbase = (NCOL == 128) ? (w & 3) * 32 : w * 16;
    const int cbase = (NCOL == 128) ? (w >> 2) * 64 : 0;

    float acc[MT][NT][4];
#pragma unroll
    for (int mt = 0; mt < MT; mt++)
#pragma unroll
        for (int nt = 0; nt < NT; nt++)
#pragma unroll
            for (int i = 0; i < 4; i++) acc[mt][nt][i] = 0.f;

    for (int kc = 0; kc < K; kc += 32) {
        // stage A tile 128x32: float2 per thread-step, split to hi/lo half2
#pragma unroll
        for (int x = tid; x < 128 * 16; x += 256) {
            int r = x >> 4, kp = x & 15;
            int k = kp * 2;
            int gr = rowBase + r, gk = kc + k;
            float2 v = make_float2(0.f, 0.f);
            if (gr < NN) {
                if (gk < K0)
                    v = *(const float2*)(A0 + (size_t)gr * K0 + gk);
                else
                    v = *(const float2*)(A1 + (size_t)gr * (K - K0) + (gk - K0));
            }
            __half h0, l0, h1, l1;
            split_h(v.x, h0, l0);
            split_h(v.y, h1, l1);
            *(__half2*)&As_hi[r * HSTR + k] = __halves2half2(h0, h1);
            *(__half2*)&As_lo[r * HSTR + k] = __halves2half2(l0, l1);
        }
        // stage B tile 32xNCOL, transposed into [col][k]
#pragma unroll
        for (int x = tid; x < 32 * NCOL; x += 256) {
            int k = x / NCOL, col = x % NCOL;
            int gk = kc + k;
            float v = (gk < K0) ? B0[gk * NCOL + col]
                                : B1[(gk - K0) * NCOL + col];
            __half h, l;
            split_h(v, h, l);
            Bs_hi[col * HSTR + k] = h;
            Bs_lo[col * HSTR + k] = l;
        }
        __syncthreads();

#pragma unroll
        for (int k16 = 0; k16 < 2; k16++) {
            const int kk = k16 * 16;
            // A fragments (hoisted across B groups)
            uint32_t ah[MT][4], al[MT][4];
#pragma unroll
            for (int mt = 0; mt < MT; mt++) {
                int r0 = rbase + mt * 16 + g;
                const __half* ph = As_hi + kk + 2 * t;
                const __half* pl = As_lo + kk + 2 * t;
                ah[mt][0] = *(const uint32_t*)(ph + r0 * HSTR);
                ah[mt][1] = *(const uint32_t*)(ph + (r0 + 8) * HSTR);
                ah[mt][2] = *(const uint32_t*)(ph + r0 * HSTR + 8);
                ah[mt][3] = *(const uint32_t*)(ph + (r0 + 8) * HSTR + 8);
                al[mt][0] = *(const uint32_t*)(pl + r0 * HSTR);
                al[mt][1] = *(const uint32_t*)(pl + (r0 + 8) * HSTR);
                al[mt][2] = *(const uint32_t*)(pl + r0 * HSTR + 8);
                al[mt][3] = *(const uint32_t*)(pl + (r0 + 8) * HSTR + 8);
            }
#pragma unroll
            for (int ng = 0; ng < NT / NTG; ng++) {
                uint32_t bh[NTG][2], bl[NTG][2];
#pragma unroll
                for (int j = 0; j < NTG; j++) {
                    int col = cbase + (ng * NTG + j) * 8 + g;
                    const __half* ph = Bs_hi + col * HSTR + kk + 2 * t;
                    const __half* pl = Bs_lo + col * HSTR + kk + 2 * t;
                    bh[j][0] = *(const uint32_t*)(ph);
                    bh[j][1] = *(const uint32_t*)(ph + 8);
                    bl[j][0] = *(const uint32_t*)(pl);
                    bl[j][1] = *(const uint32_t*)(pl + 8);
                }
#pragma unroll
                for (int mt = 0; mt < MT; mt++) {
#pragma unroll
                    for (int j = 0; j < NTG; j++) {
                        float* a = acc[mt][ng * NTG + j];
                        mma_fp16(a, ah[mt][0], ah[mt][1], ah[mt][2], ah[mt][3],
                                 bh[j][0], bh[j][1]);
                        mma_fp16(a, ah[mt][0], ah[mt][1], ah[mt][2], ah[mt][3],
                                 bl[j][0], bl[j][1]);
                        mma_fp16(a, al[mt][0], al[mt][1], al[mt][2], al[mt][3],
                                 bh[j][0], bh[j][1]);
                    }
                }
            }
        }
        __syncthreads();
    }

    // epilogue: bias + optional relu, write float2 pairs
#pragma unroll
    for (int mt = 0; mt < MT; mt++) {
#pragma unroll
        for (int nt = 0; nt < NT; nt++) {
            int col = cbase + nt * 8 + t * 2;
            float b0 = bias[col], b1 = bias[col + 1];
#pragma unroll
            for (int half = 0; half < 2; half++) {
                int gr = rowBase + rbase + mt * 16 + g + half * 8;
                if (gr < NN) {
                    float v0 = acc[mt][nt][half * 2 + 0] + b0;
                    float v1 = acc[mt][nt][half * 2 + 1] + b1;
                    if (RELU) { v0 = fmaxf(v0, 0.f); v1 = fmaxf(v1, 0.f); }
                    *(float2*)(out + (size_t)gr * NCOL + col) = make_float2(v0, v1);
                }
            }
        }
    }
}

// ---------------- launch ----------------
extern "C" void kernel_launch(void* const* d_in, const int* in_sizes, int n_in,
                              void* d_out, int out_size) {
    const float* features = (const float*)d_in[0];
    const float* Wn1 = (const float*)d_in[1];
    const float* Ws1 = (const float*)d_in[2];
    const float* b1  = (const float*)d_in[3];
    const float* Wn2 = (const float*)d_in[4];
    const float* Ws2 = (const float*)d_in[5];
    const float* b2  = (const float*)d_in[6];
    const float* Wm1 = (const float*)d_in[7];
    const float* bm1 = (const float*)d_in[8];
    const float* Wm2 = (const float*)d_in[9];
    const float* bm2 = (const float*)d_in[10];
    const void*  src = d_in[11];
    const void*  dst = d_in[12];
    float* out = (float*)d_out;

    float *p_h1, *p_h2, *p_x1, *p_x2, *p_x3;
    cudaGetSymbolAddress((void**)&p_h1, g_h1);
    cudaGetSymbolAddress((void**)&p_h2, g_h2);
    cudaGetSymbolAddress((void**)&p_x1, g_x1);
    cudaGetSymbolAddress((void**)&p_x2, g_x2);
    cudaGetSymbolAddress((void**)&p_x3, g_x3);

    const int GEMM_BLOCKS = (NN + 127) / 128;  // 782
    const int EB = (EE + 255) / 256;
    const int NB = (NN + 1023) / 1024;         // 98 scan blocks

    // CSR build
    k_detect<<<1, 32>>>(src);
    k_zero_deg<<<(NN + 255) / 256, 256>>>();
    k_count<<<EB, 256>>>(dst);
    k_scan1<<<NB, 1024>>>();
    k_scan2<<<1, 128>>>(NB);
    k_scan3<<<NB, 1024>>>();
    k_fill<<<EB, 256>>>(src, dst);

    // layer 1: mean-aggregate features (64-wide), then fused dense
    k_gather<16><<<(NN * 16 + 255) / 256, 256>>>((const float4*)features, (float4*)p_h1);
    k_gemm_fp16x2<128, 64, 128, true><<<GEMM_BLOCKS, 256>>>(features, p_h1, Ws1, Wn1, b1, p_x1);

    // layer 2: mean-aggregate x1 (128-wide), then fused dense
    k_gather<32><<<(NN * 32 + 255) / 256, 256>>>((const float4*)p_x1, (float4*)p_h2);
    k_gemm_fp16x2<256, 128, 128, true><<<GEMM_BLOCKS, 256>>>(p_x1, p_h2, Ws2, Wn2, b2, p_x2);

    // MLP head
    k_gemm_fp16x2<128, 128, 128, true ><<<GEMM_BLOCKS, 256>>>(p_x2, p_x2, Wm1, Wm1, bm1, p_x3);
    k_gemm_fp16x2<128, 128, 64,  false><<<GEMM_BLOCKS, 256>>>(p_x3, p_x3, Wm2, Wm2, bm2, out);
}

// round 7
// speedup vs baseline: 3.0712x; 1.1935x over previous
#include <cuda_runtime.h>
#include <cuda_fp16.h>
#include <stdint.h>

#define NN 100000
#define EE 1600000
// dims: IN=64, HID=128, OUT=64

// ---------------- device scratch (no allocation allowed) ----------------
__device__ int g_idx64;
__device__ __align__(16) int    g_deg[NN];
__device__ __align__(16) int    g_rowstart[NN + 1];
__device__ __align__(16) int    g_cur[NN];
__device__ __align__(16) int    g_adj[EE];
__device__ __align__(16) int    g_blocksum[128];
__device__ __align__(16) int    g_blockoff[128];
__device__ __align__(16) __half g_fh [(size_t)NN * 64];   // fp16 copy of features
__device__ __align__(16) float  g_h1 [(size_t)NN * 64];   // mean-aggregated features
__device__ __align__(16) float  g_x1 [(size_t)NN * 128];
__device__ __align__(16) __half g_x1h[(size_t)NN * 128];  // fp16 copy of x1
__device__ __align__(16) float  g_h2 [(size_t)NN * 128];  // mean-aggregated x1
__device__ __align__(16) float  g_x2 [(size_t)NN * 128];
__device__ __align__(16) float  g_x3 [(size_t)NN * 128];

// ---------------- index dtype detection ----------------
__global__ void k_detect(const void* srcp) {
    const long long* s = (const long long*)srcp;
    int lane = threadIdx.x;
    long long v = s[lane];
    int ok = (v >= 0 && v < NN) ? 1 : 0;
    ok = __all_sync(~0u, ok);
    if (lane == 0) g_idx64 = ok;
}

__global__ void k_zero_deg() {
    int n = blockIdx.x * blockDim.x + threadIdx.x;
    if (n < NN) g_deg[n] = 0;
}

// features (fp32) -> g_fh (fp16), 2 elems per thread
__global__ void k_cvt_fh(const float2* __restrict__ f) {
    int i = blockIdx.x * blockDim.x + threadIdx.x;
    if (i >= NN * 64 / 2) return;
    float2 v = f[i];
    *(__half2*)&g_fh[(size_t)i * 2] = __floats2half2_rn(v.x, v.y);
}

__device__ __forceinline__ int load_idx(const void* p, int e) {
    return g_idx64 ? (int)((const long long*)p)[e] : ((const int*)p)[e];
}

// ---------------- CSR build: count, 3-phase scan, fill ----------------
__global__ void k_count(const void* dstp) {
    int e = blockIdx.x * blockDim.x + threadIdx.x;
    if (e >= EE) return;
    atomicAdd(&g_deg[load_idx(dstp, e)], 1);
}

__global__ __launch_bounds__(1024) void k_scan1() {
    __shared__ int ws[32];
    int t = threadIdx.x, lane = t & 31, wid = t >> 5;
    int idx = blockIdx.x * 1024 + t;
    int s = (idx < NN) ? g_deg[idx] : 0;
#pragma unroll
    for (int o = 16; o > 0; o >>= 1) s += __shfl_down_sync(~0u, s, o);
    if (lane == 0) ws[wid] = s;
    __syncthreads();
    if (wid == 0) {
        int x = ws[lane];
#pragma unroll
        for (int o = 16; o > 0; o >>= 1) x += __shfl_down_sync(~0u, x, o);
        if (lane == 0) g_blocksum[blockIdx.x] = x;
    }
}

__global__ __launch_bounds__(128) void k_scan2(int nb) {
    __shared__ int ws[4];
    int t = threadIdx.x, lane = t & 31, wid = t >> 5;
    int v = (t < nb) ? g_blocksum[t] : 0;
    int inc = v;
#pragma unroll
    for (int o = 1; o < 32; o <<= 1) {
        int n = __shfl_up_sync(~0u, inc, o);
        if (lane >= o) inc += n;
    }
    if (lane == 31) ws[wid] = inc;
    __syncthreads();
    int add = 0;
    for (int i = 0; i < wid; i++) add += ws[i];
    if (t < nb) g_blockoff[t] = inc - v + add;  // exclusive
}

__global__ __launch_bounds__(1024) void k_scan3() {
    __shared__ int ws[32];
    int t = threadIdx.x, lane = t & 31, wid = t >> 5;
    int idx = blockIdx.x * 1024 + t;
    int v = (idx < NN) ? g_deg[idx] : 0;
    int inc = v;
#pragma unroll
    for (int o = 1; o < 32; o <<= 1) {
        int n = __shfl_up_sync(~0u, inc, o);
        if (lane >= o) inc += n;
    }
    if (lane == 31) ws[wid] = inc;
    __syncthreads();
    if (wid == 0) {
        int x = ws[lane];
#pragma unroll
        for (int o = 1; o < 32; o <<= 1) {
            int n = __shfl_up_sync(~0u, x, o);
            if (lane >= o) x += n;
        }
        ws[lane] = x;
    }
    __syncthreads();
    int exc = inc - v + (wid > 0 ? ws[wid - 1] : 0) + g_blockoff[blockIdx.x];
    if (idx < NN) {
        g_rowstart[idx] = exc;
        g_cur[idx] = exc;
    }
    if (idx == NN - 1) g_rowstart[NN] = EE;
}

__global__ void k_fill(const void* srcp, const void* dstp) {
    int e = blockIdx.x * blockDim.x + threadIdx.x;
    if (e >= EE) return;
    int s = load_idx(srcp, e);
    int d = load_idx(dstp, e);
    int pos = atomicAdd(&g_cur[d], 1);
    g_adj[pos] = s;
}

// ---------------- fp16 gather aggregation: h[n] = mean_{s in adj[n]} x[s] --
// LANES threads per node, 8 halves (16 B) per lane; fp32 accumulation.
template <int LANES>
__global__ void k_gather_h(const uint4* __restrict__ x, float4* __restrict__ h) {
    int tid = blockIdx.x * blockDim.x + threadIdx.x;
    int node = tid / LANES;
    int l = tid % LANES;
    if (node >= NN) return;
    int i = g_rowstart[node];
    const int end = g_rowstart[node + 1];
    const int deg = end - i;
    float acc[8];
#pragma unroll
    for (int j = 0; j < 8; j++) acc[j] = 0.f;
#pragma unroll 1
    for (; i + 4 <= end; i += 4) {
        int n0 = g_adj[i], n1 = g_adj[i + 1], n2 = g_adj[i + 2], n3 = g_adj[i + 3];
        uint4 v0 = x[(size_t)n0 * LANES + l];
        uint4 v1 = x[(size_t)n1 * LANES + l];
        uint4 v2 = x[(size_t)n2 * LANES + l];
        uint4 v3 = x[(size_t)n3 * LANES + l];
        const uint32_t* vs[4] = {&v0.x, &v1.x, &v2.x, &v3.x};
#pragma unroll
        for (int q = 0; q < 4; q++) {
#pragma unroll
            for (int j = 0; j < 4; j++) {
                float2 f = __half22float2(*(const __half2*)&vs[q][j]);
                acc[2 * j] += f.x;
                acc[2 * j + 1] += f.y;
            }
        }
    }
    for (; i < end; i++) {
        uint4 v = x[(size_t)g_adj[i] * LANES + l];
        const uint32_t* vp = &v.x;
#pragma unroll
        for (int j = 0; j < 4; j++) {
            float2 f = __half22float2(*(const __half2*)&vp[j]);
            acc[2 * j] += f.x;
            acc[2 * j + 1] += f.y;
        }
    }
    float inv = 1.f / (float)max(deg, 1);
#pragma unroll
    for (int j = 0; j < 8; j++) acc[j] *= inv;
    h[(size_t)node * LANES * 2 + 2 * l] =
        make_float4(acc[0], acc[1], acc[2], acc[3]);
    h[(size_t)node * LANES * 2 + 2 * l + 1] =
        make_float4(acc[4], acc[5], acc[6], acc[7]);
}

// ---------------- FP16x2-split tensor-core fused dense layer ----------------
// out[r][:] = act( [A0[r] | A1[r]] @ [B0;B1] + bias ),  A split once at staging.
// A-tile register prefetch hides next chunk's global latency under MMA.

__device__ __forceinline__ void mma_fp16(float c[4], uint32_t a0, uint32_t a1,
                                         uint32_t a2, uint32_t a3,
                                         uint32_t b0, uint32_t b1) {
    asm volatile(
        "mma.sync.aligned.m16n8k16.row.col.f32.f16.f16.f32 "
        "{%0,%1,%2,%3}, {%4,%5,%6,%7}, {%8,%9}, {%0,%1,%2,%3};"
        : "+f"(c[0]), "+f"(c[1]), "+f"(c[2]), "+f"(c[3])
        : "r"(a0), "r"(a1), "r"(a2), "r"(a3), "r"(b0), "r"(b1));
}

__device__ __forceinline__ void split_h(float x, __half& hi, __half& lo) {
    hi = __float2half_rn(x);
    lo = __float2half_rn(x - __half2float(hi));
}

#define HSTR 40  // fragment LDS bank = (4g+t) mod 32, all lanes distinct

template <int K, int K0, int NCOL, bool RELU, bool WH>
__global__ __launch_bounds__(256, 2) void k_gemm_fp16x2(
    const float* __restrict__ A0, const float* __restrict__ A1,
    const float* __restrict__ B0, const float* __restrict__ B1,
    const float* __restrict__ bias, float* __restrict__ out,
    __half* __restrict__ outh) {
    constexpr int MT = (NCOL == 128) ? 2 : 1;
    constexpr int NT = 8;
    constexpr int NTG = 4;

    __shared__ __half As_hi[128 * HSTR];
    __shared__ __half As_lo[128 * HSTR];
    __shared__ __half Bs_hi[NCOL * HSTR];   // transposed: [col][k]
    __shared__ __half Bs_lo[NCOL * HSTR];

    const int tid = threadIdx.x;
    const int w = tid >> 5;
    const int lane = tid & 31;
    const int g = lane >> 2;
    const int t = lane & 3;
    const int rowBase = blockIdx.x * 128;

    const int rbase = (NCOL == 128) ? (w & 3) * 32 : w * 16;
    const int cbase = (NCOL == 128) ? (w >> 2) * 64 : 0;

    float acc[MT][NT][4];
#pragma unroll
    for (int mt = 0; mt < MT; mt++)
#pragma unroll
        for (int nt = 0; nt < NT; nt++)
#pragma unroll
            for (int i = 0; i < 4; i++) acc[mt][nt][i] = 0.f;

    // A prefetch registers: 8 float2 per thread per 32-k chunk
    float2 pa[8];
    auto loadA = [&](int kc) {
#pragma unroll
        for (int it = 0; it < 8; it++) {
            int x = tid + it * 256;
            int r = x >> 4, k = (x & 15) * 2;
            int gr = rowBase + r, gk = kc + k;
            float2 v = make_float2(0.f, 0.f);
            if (gr < NN) {
                if (gk < K0)
                    v = *(const float2*)(A0 + (size_t)gr * K0 + gk);
                else
                    v = *(const float2*)(A1 + (size_t)gr * (K - K0) + (gk - K0));
            }
            pa[it] = v;
        }
    };

    loadA(0);
    for (int kc = 0; kc < K; kc += 32) {
        // stage A from prefetch regs, split hi/lo
#pragma unroll
        for (int it = 0; it < 8; it++) {
            int x = tid + it * 256;
            int r = x >> 4, k = (x & 15) * 2;
            __half h0, l0, h1, l1;
            split_h(pa[it].x, h0, l0);
            split_h(pa[it].y, h1, l1);
            *(__half2*)&As_hi[r * HSTR + k] = __halves2half2(h0, h1);
            *(__half2*)&As_lo[r * HSTR + k] = __halves2half2(l0, l1);
        }
        // stage B tile 32xNCOL, transposed into [col][k]
#pragma unroll
        for (int x = tid; x < 32 * NCOL; x += 256) {
            int k = x / NCOL, col = x % NCOL;
            int gk = kc + k;
            float v = (gk < K0) ? B0[gk * NCOL + col]
                                : B1[(gk - K0) * NCOL + col];
            __half h, l;
            split_h(v, h, l);
            Bs_hi[col * HSTR + k] = h;
            Bs_lo[col * HSTR + k] = l;
        }
        __syncthreads();

        if (kc + 32 < K) loadA(kc + 32);  // latency overlaps MMA below

#pragma unroll
        for (int k16 = 0; k16 < 2; k16++) {
            const int kk = k16 * 16;
            uint32_t ah[MT][4], al[MT][4];
#pragma unroll
            for (int mt = 0; mt < MT; mt++) {
                int r0 = rbase + mt * 16 + g;
                const __half* ph = As_hi + kk + 2 * t;
                const __half* pl = As_lo + kk + 2 * t;
                ah[mt][0] = *(const uint32_t*)(ph + r0 * HSTR);
                ah[mt][1] = *(const uint32_t*)(ph + (r0 + 8) * HSTR);
                ah[mt][2] = *(const uint32_t*)(ph + r0 * HSTR + 8);
                ah[mt][3] = *(const uint32_t*)(ph + (r0 + 8) * HSTR + 8);
                al[mt][0] = *(const uint32_t*)(pl + r0 * HSTR);
                al[mt][1] = *(const uint32_t*)(pl + (r0 + 8) * HSTR);
                al[mt][2] = *(const uint32_t*)(pl + r0 * HSTR + 8);
                al[mt][3] = *(const uint32_t*)(pl + (r0 + 8) * HSTR + 8);
            }
#pragma unroll
            for (int ng = 0; ng < NT / NTG; ng++) {
                uint32_t bh[NTG][2], bl[NTG][2];
#pragma unroll
                for (int j = 0; j < NTG; j++) {
                    int col = cbase + (ng * NTG + j) * 8 + g;
                    const __half* ph = Bs_hi + col * HSTR + kk + 2 * t;
                    const __half* pl = Bs_lo + col * HSTR + kk + 2 * t;
                    bh[j][0] = *(const uint32_t*)(ph);
                    bh[j][1] = *(const uint32_t*)(ph + 8);
                    bl[j][0] = *(const uint32_t*)(pl);
                    bl[j][1] = *(const uint32_t*)(pl + 8);
                }
#pragma unroll
                for (int mt = 0; mt < MT; mt++) {
#pragma unroll
                    for (int j = 0; j < NTG; j++) {
                        float* a = acc[mt][ng * NTG + j];
                        mma_fp16(a, ah[mt][0], ah[mt][1], ah[mt][2], ah[mt][3],
                                 bh[j][0], bh[j][1]);
                        mma_fp16(a, ah[mt][0], ah[mt][1], ah[mt][2], ah[mt][3],
                                 bl[j][0], bl[j][1]);
                        mma_fp16(a, al[mt][0], al[mt][1], al[mt][2], al[mt][3],
                                 bh[j][0], bh[j][1]);
                    }
                }
            }
        }
        __syncthreads();
    }

    // epilogue: bias + optional relu; fp32 out + optional fp16 copy
#pragma unroll
    for (int mt = 0; mt < MT; mt++) {
#pragma unroll
        for (int nt = 0; nt < NT; nt++) {
            int col = cbase + nt * 8 + t * 2;
            float b0 = bias[col], b1 = bias[col + 1];
#pragma unroll
            for (int half = 0; half < 2; half++) {
                int gr = rowBase + rbase + mt * 16 + g + half * 8;
                if (gr < NN) {
                    float v0 = acc[mt][nt][half * 2 + 0] + b0;
                    float v1 = acc[mt][nt][half * 2 + 1] + b1;
                    if (RELU) { v0 = fmaxf(v0, 0.f); v1 = fmaxf(v1, 0.f); }
                    *(float2*)(out + (size_t)gr * NCOL + col) = make_float2(v0, v1);
                    if (WH)
                        *(__half2*)(outh + (size_t)gr * NCOL + col) =
                            __floats2half2_rn(v0, v1);
                }
            }
        }
    }
}

// ---------------- launch ----------------
extern "C" void kernel_launch(void* const* d_in, const int* in_sizes, int n_in,
                              void* d_out, int out_size) {
    const float* features = (const float*)d_in[0];
    const float* Wn1 = (const float*)d_in[1];
    const float* Ws1 = (const float*)d_in[2];
    const float* b1  = (const float*)d_in[3];
    const float* Wn2 = (const float*)d_in[4];
    const float* Ws2 = (const float*)d_in[5];
    const float* b2  = (const float*)d_in[6];
    const float* Wm1 = (const float*)d_in[7];
    const float* bm1 = (const float*)d_in[8];
    const float* Wm2 = (const float*)d_in[9];
    const float* bm2 = (const float*)d_in[10];
    const void*  src = d_in[11];
    const void*  dst = d_in[12];
    float* out = (float*)d_out;

    float *p_h1, *p_h2, *p_x1, *p_x2, *p_x3;
    __half *p_fh, *p_x1h;
    cudaGetSymbolAddress((void**)&p_h1, g_h1);
    cudaGetSymbolAddress((void**)&p_h2, g_h2);
    cudaGetSymbolAddress((void**)&p_x1, g_x1);
    cudaGetSymbolAddress((void**)&p_x2, g_x2);
    cudaGetSymbolAddress((void**)&p_x3, g_x3);
    cudaGetSymbolAddress((void**)&p_fh, g_fh);
    cudaGetSymbolAddress((void**)&p_x1h, g_x1h);

    const int GEMM_BLOCKS = (NN + 127) / 128;  // 782
    const int EB = (EE + 255) / 256;
    const int NB = (NN + 1023) / 1024;         // 98 scan blocks

    // CSR build + fp16 feature copy
    k_detect<<<1, 32>>>(src);
    k_zero_deg<<<(NN + 255) / 256, 256>>>();
    k_cvt_fh<<<(NN * 64 / 2 + 255) / 256, 256>>>((const float2*)features);
    k_count<<<EB, 256>>>(dst);
    k_scan1<<<NB, 1024>>>();
    k_scan2<<<1, 128>>>(NB);
    k_scan3<<<NB, 1024>>>();
    k_fill<<<EB, 256>>>(src, dst);

    // layer 1: mean-aggregate fp16 features (64-wide), then fused dense
    k_gather_h<8><<<(NN * 8 + 255) / 256, 256>>>((const uint4*)p_fh, (float4*)p_h1);
    k_gemm_fp16x2<128, 64, 128, true, true><<<GEMM_BLOCKS, 256>>>(
        features, p_h1, Ws1, Wn1, b1, p_x1, p_x1h);

    // layer 2: mean-aggregate fp16 x1 (128-wide), then fused dense
    k_gather_h<16><<<(NN * 16 + 255) / 256, 256>>>((const uint4*)p_x1h, (float4*)p_h2);
    k_gemm_fp16x2<256, 128, 128, true, false><<<GEMM_BLOCKS, 256>>>(
        p_x1, p_h2, Ws2, Wn2, b2, p_x2, nullptr);

    // MLP head
    k_gemm_fp16x2<128, 128, 128, true,  false><<<GEMM_BLOCKS, 256>>>(
        p_x2, p_x2, Wm1, Wm1, bm1, p_x3, nullptr);
    k_gemm_fp16x2<128, 128, 64,  false, false><<<GEMM_BLOCKS, 256>>>(
        p_x3, p_x3, Wm2, Wm2, bm2, out, nullptr);
}

// round 11
// speedup vs baseline: 3.4945x; 1.1378x over previous
#include <cuda_runtime.h>
#include <cuda_fp16.h>
#include <stdint.h>

#define NN 100000
#define EE 1600000
// dims: IN=64, HID=128, OUT=64

// ---------------- device scratch (no allocation allowed) ----------------
__device__ int g_idx64;
__device__ __align__(16) int    g_deg[NN];
__device__ __align__(16) int    g_rowstart[NN + 1];
__device__ __align__(16) int    g_cur[NN];
__device__ __align__(16) int    g_adj[EE];
__device__ __align__(16) int    g_blocksum[128];
__device__ __align__(16) int    g_blockoff[128];
// all GEMM operands pre-split to fp16 hi/lo
__device__ __align__(16) __half g_fh [(size_t)NN * 64];
__device__ __align__(16) __half g_fl [(size_t)NN * 64];
__device__ __align__(16) __half g_h1h[(size_t)NN * 64];
__device__ __align__(16) __half g_h1l[(size_t)NN * 64];
__device__ __align__(16) __half g_x1h[(size_t)NN * 128];
__device__ __align__(16) __half g_x1l[(size_t)NN * 128];
__device__ __align__(16) __half g_h2h[(size_t)NN * 128];
__device__ __align__(16) __half g_h2l[(size_t)NN * 128];
__device__ __align__(16) __half g_x2h[(size_t)NN * 128];
__device__ __align__(16) __half g_x2l[(size_t)NN * 128];
__device__ __align__(16) __half g_x3h[(size_t)NN * 128];
__device__ __align__(16) __half g_x3l[(size_t)NN * 128];
// weight arenas, pre-split + pre-transposed to [col][k]
// offsets: L1=0 (128*128), L2=16384 (256*128), L3=49152 (128*128), L4=65536 (128*64)
__device__ __align__(16) __half g_wh[73728];
__device__ __align__(16) __half g_wl[73728];

// ---------------- small helpers ----------------
__device__ __forceinline__ void split_h(float x, __half& hi, __half& lo) {
    hi = __float2half_rn(x);
    lo = __float2half_rn(x - __half2float(hi));
}

// ---------------- index dtype detection ----------------
__global__ void k_detect(const void* srcp) {
    const long long* s = (const long long*)srcp;
    int lane = threadIdx.x;
    long long v = s[lane];
    int ok = (v >= 0 && v < NN) ? 1 : 0;
    ok = __all_sync(~0u, ok);
    if (lane == 0) g_idx64 = ok;
}

__global__ void k_zero_deg() {
    int n = blockIdx.x * blockDim.x + threadIdx.x;
    if (n < NN) g_deg[n] = 0;
}

// features (fp32) -> hi/lo fp16
__global__ void k_cvt_f(const float2* __restrict__ f) {
    int i = blockIdx.x * blockDim.x + threadIdx.x;
    if (i >= NN * 32) return;
    float2 v = f[i];
    __half h0, l0, h1, l1;
    split_h(v.x, h0, l0);
    split_h(v.y, h1, l1);
    *(__half2*)&g_fh[(size_t)i * 2] = __halves2half2(h0, h1);
    *(__half2*)&g_fl[(size_t)i * 2] = __halves2half2(l0, l1);
}

// weights: split + transpose into [col][k] arena slice
template <int K, int K0, int NCOL>
__global__ void k_prep_w(const float* __restrict__ B0, const float* __restrict__ B1,
                         int off) {
    int i = blockIdx.x * blockDim.x + threadIdx.x;
    if (i >= K * NCOL) return;
    int col = i / K, k = i % K;
    float v = (k < K0) ? B0[k * NCOL + col] : B1[(k - K0) * NCOL + col];
    __half h, l;
    split_h(v, h, l);
    g_wh[off + col * K + k] = h;
    g_wl[off + col * K + k] = l;
}

__device__ __forceinline__ int load_idx(const void* p, int e) {
    return g_idx64 ? (int)((const long long*)p)[e] : ((const int*)p)[e];
}

// ---------------- CSR build: count, 3-phase scan, fill ----------------
__global__ void k_count(const void* dstp) {
    int e = blockIdx.x * blockDim.x + threadIdx.x;
    if (e >= EE) return;
    atomicAdd(&g_deg[load_idx(dstp, e)], 1);
}

__global__ __launch_bounds__(1024) void k_scan1() {
    __shared__ int ws[32];
    int t = threadIdx.x, lane = t & 31, wid = t >> 5;
    int idx = blockIdx.x * 1024 + t;
    int s = (idx < NN) ? g_deg[idx] : 0;
#pragma unroll
    for (int o = 16; o > 0; o >>= 1) s += __shfl_down_sync(~0u, s, o);
    if (lane == 0) ws[wid] = s;
    __syncthreads();
    if (wid == 0) {
        int x = ws[lane];
#pragma unroll
        for (int o = 16; o > 0; o >>= 1) x += __shfl_down_sync(~0u, x, o);
        if (lane == 0) g_blocksum[blockIdx.x] = x;
    }
}

__global__ __launch_bounds__(128) void k_scan2(int nb) {
    __shared__ int ws[4];
    int t = threadIdx.x, lane = t & 31, wid = t >> 5;
    int v = (t < nb) ? g_blocksum[t] : 0;
    int inc = v;
#pragma unroll
    for (int o = 1; o < 32; o <<= 1) {
        int n = __shfl_up_sync(~0u, inc, o);
        if (lane >= o) inc += n;
    }
    if (lane == 31) ws[wid] = inc;
    __syncthreads();
    int add = 0;
    for (int i = 0; i < wid; i++) add += ws[i];
    if (t < nb) g_blockoff[t] = inc - v + add;  // exclusive
}

__global__ __launch_bounds__(1024) void k_scan3() {
    __shared__ int ws[32];
    int t = threadIdx.x, lane = t & 31, wid = t >> 5;
    int idx = blockIdx.x * 1024 + t;
    int v = (idx < NN) ? g_deg[idx] : 0;
    int inc = v;
#pragma unroll
    for (int o = 1; o < 32; o <<= 1) {
        int n = __shfl_up_sync(~0u, inc, o);
        if (lane >= o) inc += n;
    }
    if (lane == 31) ws[wid] = inc;
    __syncthreads();
    if (wid == 0) {
        int x = ws[lane];
#pragma unroll
        for (int o = 1; o < 32; o <<= 1) {
            int n = __shfl_up_sync(~0u, x, o);
            if (lane >= o) x += n;
        }
        ws[lane] = x;
    }
    __syncthreads();
    int exc = inc - v + (wid > 0 ? ws[wid - 1] : 0) + g_blockoff[blockIdx.x];
    if (idx < NN) {
        g_rowstart[idx] = exc;
        g_cur[idx] = exc;
    }
    if (idx == NN - 1) g_rowstart[NN] = EE;
}

__global__ void k_fill(const void* srcp, const void* dstp) {
    int e = blockIdx.x * blockDim.x + threadIdx.x;
    if (e >= EE) return;
    int s = load_idx(srcp, e);
    int d = load_idx(dstp, e);
    int pos = atomicAdd(&g_cur[d], 1);
    g_adj[pos] = s;
}

// ---------------- fp16 gather aggregation -> hi/lo split output ----------
// LANES threads per node, 8 halves (16 B) per lane; fp32 accumulation.
template <int LANES>
__global__ void k_gather_h(const uint4* __restrict__ x,
                           __half* __restrict__ hh, __half* __restrict__ hl) {
    int tid = blockIdx.x * blockDim.x + threadIdx.x;
    int node = tid / LANES;
    int l = tid % LANES;
    if (node >= NN) return;
    int i = g_rowstart[node];
    const int end = g_rowstart[node + 1];
    const int deg = end - i;
    float acc[8];
#pragma unroll
    for (int j = 0; j < 8; j++) acc[j] = 0.f;
#pragma unroll 1
    for (; i + 4 <= end; i += 4) {
        int n0 = g_adj[i], n1 = g_adj[i + 1], n2 = g_adj[i + 2], n3 = g_adj[i + 3];
        uint4 v0 = x[(size_t)n0 * LANES + l];
        uint4 v1 = x[(size_t)n1 * LANES + l];
        uint4 v2 = x[(size_t)n2 * LANES + l];
        uint4 v3 = x[(size_t)n3 * LANES + l];
        const uint32_t* vs[4] = {&v0.x, &v1.x, &v2.x, &v3.x};
#pragma unroll
        for (int q = 0; q < 4; q++) {
#pragma unroll
            for (int j = 0; j < 4; j++) {
                float2 f = __half22float2(*(const __half2*)&vs[q][j]);
                acc[2 * j] += f.x;
                acc[2 * j + 1] += f.y;
            }
        }
    }
    for (; i < end; i++) {
        uint4 v = x[(size_t)g_adj[i] * LANES + l];
        const uint32_t* vp = &v.x;
#pragma unroll
        for (int j = 0; j < 4; j++) {
            float2 f = __half22float2(*(const __half2*)&vp[j]);
            acc[2 * j] += f.x;
            acc[2 * j + 1] += f.y;
        }
    }
    float inv = 1.f / (float)max(deg, 1);
    __half hv[8], lv[8];
#pragma unroll
    for (int j = 0; j < 8; j++) split_h(acc[j] * inv, hv[j], lv[j]);
    size_t o = ((size_t)node * LANES + l) * 8;
    *(uint4*)&hh[o] = *(uint4*)hv;
    *(uint4*)&hl[o] = *(uint4*)lv;
}

// ---------------- FP16x2-split tensor-core fused dense layer ----------------
// All operands pre-split hi/lo fp16 in global memory: staging is pure uint4
// copies; inner loop is pure LDS+HMMA (3-term: ah*bh + ah*bl + al*bh).
// Tile: 128 rows x NCOL cols, 256 threads, 2 CTAs/SM. Legacy mma.sync path
// (harness targets sm_100 without the 'a' suffix -> no tcgen05).

__device__ __forceinline__ void mma_fp16(float c[4], uint32_t a0, uint32_t a1,
                                         uint32_t a2, uint32_t a3,
                                         uint32_t b0, uint32_t b1) {
    asm volatile(
        "mma.sync.aligned.m16n8k16.row.col.f32.f16.f16.f32 "
        "{%0,%1,%2,%3}, {%4,%5,%6,%7}, {%8,%9}, {%0,%1,%2,%3};"
        : "+f"(c[0]), "+f"(c[1]), "+f"(c[2]), "+f"(c[3])
        : "r"(a0), "r"(a1), "r"(a2), "r"(a3), "r"(b0), "r"(b1));
}

#define HSTR 40  // fragment LDS bank = (4g+t) mod 32, all lanes distinct

template <int K, int K0, int NCOL, bool RELU, bool WH, bool WF>
__global__ __launch_bounds__(256, 2) void k_gemm_fp16s(
    const __half* __restrict__ Ah0, const __half* __restrict__ Al0,
    const __half* __restrict__ Ah1, const __half* __restrict__ Al1,
    const __half* __restrict__ Bh, const __half* __restrict__ Bl,
    const float* __restrict__ bias, float* __restrict__ out,
    __half* __restrict__ outh, __half* __restrict__ outl) {
    constexpr int MT = (NCOL == 128) ? 2 : 1;
    constexpr int NT = 8;
    constexpr int NTG = 4;

    __shared__ __half As_hi[128 * HSTR];
    __shared__ __half As_lo[128 * HSTR];
    __shared__ __half Bs_hi[NCOL * HSTR];   // [col][k]
    __shared__ __half Bs_lo[NCOL * HSTR];

    const int tid = threadIdx.x;
    const int w = tid >> 5;
    const int lane = tid & 31;
    const int g = lane >> 2;
    const int t = lane & 3;
    const int rowBase = blockIdx.x * 128;

    const int rbase = (NCOL == 128) ? (w & 3) * 32 : w * 16;
    const int cbase = (NCOL == 128) ? (w >> 2) * 64 : 0;

    float acc[MT][NT][4];
#pragma unroll
    for (int mt = 0; mt < MT; mt++)
#pragma unroll
        for (int nt = 0; nt < NT; nt++)
#pragma unroll
            for (int i = 0; i < 4; i++) acc[mt][nt][i] = 0.f;

    // A prefetch: per 32-k chunk, 128 rows x 4 uint4 (hi) + 4 (lo) = 512+512
    // uint4 total; 2 hi + 2 lo per thread.
    const int pr0 = tid >> 2, pq0 = tid & 3;          // element 0: row, quarter
    const int pr1 = (tid + 256) >> 2, pq1 = tid & 3;  // element 1
    uint4 pah[2], pal[2];
    auto loadA = [&](int kc) {
        const __half *sAh, *sAl;
        int stride;
        if (kc < K0) { sAh = Ah0; sAl = Al0; stride = K0; }
        else { sAh = Ah1; sAl = Al1; stride = K - K0; kc -= K0; }
        int gr0 = rowBase + pr0, gr1 = rowBase + pr1;
        pah[0] = pal[0] = pah[1] = pal[1] = make_uint4(0, 0, 0, 0);
        if (gr0 < NN) {
            pah[0] = *(const uint4*)(sAh + (size_t)gr0 * stride + kc + pq0 * 8);
            pal[0] = *(const uint4*)(sAl + (size_t)gr0 * stride + kc + pq0 * 8);
        }
        if (gr1 < NN) {
            pah[1] = *(const uint4*)(sAh + (size_t)gr1 * stride + kc + pq1 * 8);
            pal[1] = *(const uint4*)(sAl + (size_t)gr1 * stride + kc + pq1 * 8);
        }
    };

    loadA(0);
    for (int kc = 0; kc < K; kc += 32) {
        // stage A from prefetch regs (16B-aligned: r*80 + q*16 bytes)
        *(uint4*)&As_hi[pr0 * HSTR + pq0 * 8] = pah[0];
        *(uint4*)&As_lo[pr0 * HSTR + pq0 * 8] = pal[0];
        *(uint4*)&As_hi[pr1 * HSTR + pq1 * 8] = pah[1];
        *(uint4*)&As_lo[pr1 * HSTR + pq1 * 8] = pal[1];
        // stage B: NCOL cols x 4 uint4 (32 halves = full K-chunk) per array
#pragma unroll
        for (int x = tid; x < NCOL * 4; x += 256) {
            int c = x >> 2, q = x & 3;
            *(uint4*)&Bs_hi[c * HSTR + q * 8] =
                *(const uint4*)(Bh + (size_t)c * K + kc + q * 8);
            *(uint4*)&Bs_lo[c * HSTR + q * 8] =
                *(const uint4*)(Bl + (size_t)c * K + kc + q * 8);
        }
        __syncthreads();

        if (kc + 32 < K) loadA(kc + 32);  // latency overlaps MMA below

#pragma unroll
        for (int k16 = 0; k16 < 2; k16++) {
            const int kk = k16 * 16;
            uint32_t ah[MT][4], al[MT][4];
#pragma unroll
            for (int mt = 0; mt < MT; mt++) {
                int r0 = rbase + mt * 16 + g;
                const __half* ph = As_hi + kk + 2 * t;
                const __half* pl = As_lo + kk + 2 * t;
                ah[mt][0] = *(const uint32_t*)(ph + r0 * HSTR);
                ah[mt][1] = *(const uint32_t*)(ph + (r0 + 8) * HSTR);
                ah[mt][2] = *(const uint32_t*)(ph + r0 * HSTR + 8);
                ah[mt][3] = *(const uint32_t*)(ph + (r0 + 8) * HSTR + 8);
                al[mt][0] = *(const uint32_t*)(pl + r0 * HSTR);
                al[mt][1] = *(const uint32_t*)(pl + (r0 + 8) * HSTR);
                al[mt][2] = *(const uint32_t*)(pl + r0 * HSTR + 8);
                al[mt][3] = *(const uint32_t*)(pl + (r0 + 8) * HSTR + 8);
            }
#pragma unroll
            for (int ng = 0; ng < NT / NTG; ng++) {
                uint32_t bh[NTG][2], bl[NTG][2];
#pragma unroll
                for (int j = 0; j < NTG; j++) {
                    int col = cbase + (ng * NTG + j) * 8 + g;
                    const __half* ph = Bs_hi + col * HSTR + kk + 2 * t;
                    const __half* pl = Bs_lo + col * HSTR + kk + 2 * t;
                    bh[j][0] = *(const uint32_t*)(ph);
                    bh[j][1] = *(const uint32_t*)(ph + 8);
                    bl[j][0] = *(const uint32_t*)(pl);
                    bl[j][1] = *(const uint32_t*)(pl + 8);
                }
#pragma unroll
                for (int mt = 0; mt < MT; mt++) {
#pragma unroll
                    for (int j = 0; j < NTG; j++) {
                        float* a = acc[mt][ng * NTG + j];
                        mma_fp16(a, ah[mt][0], ah[mt][1], ah[mt][2], ah[mt][3],
                                 bh[j][0], bh[j][1]);
                        mma_fp16(a, ah[mt][0], ah[mt][1], ah[mt][2], ah[mt][3],
                                 bl[j][0], bl[j][1]);
                        mma_fp16(a, al[mt][0], al[mt][1], al[mt][2], al[mt][3],
                                 bh[j][0], bh[j][1]);
                    }
                }
            }
        }
        __syncthreads();
    }

    // epilogue: bias + optional relu; write hi/lo fp16 and/or fp32
#pragma unroll
    for (int mt = 0; mt < MT; mt++) {
#pragma unroll
        for (int nt = 0; nt < NT; nt++) {
            int col = cbase + nt * 8 + t * 2;
            float b0 = bias[col], b1 = bias[col + 1];
#pragma unroll
            for (int half = 0; half < 2; half++) {
                int gr = rowBase + rbase + mt * 16 + g + half * 8;
                if (gr < NN) {
                    float v0 = acc[mt][nt][half * 2 + 0] + b0;
                    float v1 = acc[mt][nt][half * 2 + 1] + b1;
                    if (RELU) { v0 = fmaxf(v0, 0.f); v1 = fmaxf(v1, 0.f); }
                    if (WF)
                        *(float2*)(out + (size_t)gr * NCOL + col) =
                            make_float2(v0, v1);
                    if (WH) {
                        __half h0, l0, h1, l1;
                        split_h(v0, h0, l0);
                        split_h(v1, h1, l1);
                        *(__half2*)(outh + (size_t)gr * NCOL + col) =
                            __halves2half2(h0, h1);
                        *(__half2*)(outl + (size_t)gr * NCOL + col) =
                            __halves2half2(l0, l1);
                    }
                }
            }
        }
    }
}

// ---------------- launch ----------------
extern "C" void kernel_launch(void* const* d_in, const int* in_sizes, int n_in,
                              void* d_out, int out_size) {
    const float* features = (const float*)d_in[0];
    const float* Wn1 = (const float*)d_in[1];
    const float* Ws1 = (const float*)d_in[2];
    const float* b1  = (const float*)d_in[3];
    const float* Wn2 = (const float*)d_in[4];
    const float* Ws2 = (const float*)d_in[5];
    const float* b2  = (const float*)d_in[6];
    const float* Wm1 = (const float*)d_in[7];
    const float* bm1 = (const float*)d_in[8];
    const float* Wm2 = (const float*)d_in[9];
    const float* bm2 = (const float*)d_in[10];
    const void*  src = d_in[11];
    const void*  dst = d_in[12];
    float* out = (float*)d_out;

    __half *p_fh, *p_fl, *p_h1h, *p_h1l, *p_x1h, *p_x1l;
    __half *p_h2h, *p_h2l, *p_x2h, *p_x2l, *p_x3h, *p_x3l, *p_wh, *p_wl;
    cudaGetSymbolAddress((void**)&p_fh, g_fh);
    cudaGetSymbolAddress((void**)&p_fl, g_fl);
    cudaGetSymbolAddress((void**)&p_h1h, g_h1h);
    cudaGetSymbolAddress((void**)&p_h1l, g_h1l);
    cudaGetSymbolAddress((void**)&p_x1h, g_x1h);
    cudaGetSymbolAddress((void**)&p_x1l, g_x1l);
    cudaGetSymbolAddress((void**)&p_h2h, g_h2h);
    cudaGetSymbolAddress((void**)&p_h2l, g_h2l);
    cudaGetSymbolAddress((void**)&p_x2h, g_x2h);
    cudaGetSymbolAddress((void**)&p_x2l, g_x2l);
    cudaGetSymbolAddress((void**)&p_x3h, g_x3h);
    cudaGetSymbolAddress((void**)&p_x3l, g_x3l);
    cudaGetSymbolAddress((void**)&p_wh, g_wh);
    cudaGetSymbolAddress((void**)&p_wl, g_wl);

    const int GEMM_BLOCKS = (NN + 127) / 128;  // 782
    const int EB = (EE + 255) / 256;
    const int NB = (NN + 1023) / 1024;

    // prep: detect, feature split, weight split/transpose, CSR
    k_detect<<<1, 32>>>(src);
    k_zero_deg<<<(NN + 255) / 256, 256>>>();
    k_cvt_f<<<(NN * 32 + 255) / 256, 256>>>((const float2*)features);
    k_prep_w<128, 64, 128><<<(128 * 128 + 255) / 256, 256>>>(Ws1, Wn1, 0);
    k_prep_w<256, 128, 128><<<(256 * 128 + 255) / 256, 256>>>(Ws2, Wn2, 16384);
    k_prep_w<128, 128, 128><<<(128 * 128 + 255) / 256, 256>>>(Wm1, Wm1, 49152);
    k_prep_w<128, 128, 64><<<(128 * 64 + 255) / 256, 256>>>(Wm2, Wm2, 65536);
    k_count<<<EB, 256>>>(dst);
    k_scan1<<<NB, 1024>>>();
    k_scan2<<<1, 128>>>(NB);
    k_scan3<<<NB, 1024>>>();
    k_fill<<<EB, 256>>>(src, dst);

    // layer 1
    k_gather_h<8><<<(NN * 8 + 255) / 256, 256>>>((const uint4*)p_fh, p_h1h, p_h1l);
    k_gemm_fp16s<128, 64, 128, true, true, false><<<GEMM_BLOCKS, 256>>>(
        p_fh, p_fl, p_h1h, p_h1l, p_wh, p_wl, b1, nullptr, p_x1h, p_x1l);

    // layer 2
    k_gather_h<16><<<(NN * 16 + 255) / 256, 256>>>((const uint4*)p_x1h, p_h2h, p_h2l);
    k_gemm_fp16s<256, 128, 128, true, true, false><<<GEMM_BLOCKS, 256>>>(
        p_x1h, p_x1l, p_h2h, p_h2l, p_wh + 16384, p_wl + 16384, b2,
        nullptr, p_x2h, p_x2l);

    // MLP head
    k_gemm_fp16s<128, 128, 128, true, true, false><<<GEMM_BLOCKS, 256>>>(
        p_x2h, p_x2l, p_x2h, p_x2l, p_wh + 49152, p_wl + 49152, bm1,
        nullptr, p_x3h, p_x3l);
    k_gemm_fp16s<128, 128, 64, false, false, true><<<GEMM_BLOCKS, 256>>>(
        p_x3h, p_x3l, p_x3h, p_x3l, p_wh + 65536, p_wl + 65536, bm2,
        out, nullptr, nullptr);
}